// round 8
// baseline (speedup 1.0000x reference)
#include <cuda_runtime.h>
#include <cuda_bf16.h>
#include <math.h>

#define Bsz 2
#define Sdim 2048
#define Edim 1024
#define Hn 16
#define DHd 64
#define Adim 1024
#define Mrows (Bsz * Sdim)  // 4096

typedef unsigned short ushort_t;

// Scratch (allocation-free rule: __device__ globals)
__device__ __align__(256) float    g_Q [(size_t)Bsz * Hn * Sdim * DHd];
__device__ __align__(256) ushort_t g_Kh[(size_t)Bsz * Hn * Sdim * DHd];
__device__ __align__(256) ushort_t g_Kl[(size_t)Bsz * Hn * Sdim * DHd];
__device__ __align__(256) ushort_t g_Vh[(size_t)Bsz * Hn * Sdim * DHd];
__device__ __align__(256) ushort_t g_Vl[(size_t)Bsz * Hn * Sdim * DHd];
__device__ __align__(256) ushort_t g_Oh[(size_t)Bsz * Sdim * Adim];
__device__ __align__(256) ushort_t g_Ol[(size_t)Bsz * Sdim * Adim];
// pre-split inputs
__device__ __align__(256) ushort_t g_xh[(size_t)Mrows * Edim];
__device__ __align__(256) ushort_t g_xl[(size_t)Mrows * Edim];
__device__ __align__(256) ushort_t g_Wqh[(size_t)Hn * Edim * DHd];
__device__ __align__(256) ushort_t g_Wql[(size_t)Hn * Edim * DHd];
__device__ __align__(256) ushort_t g_Wkh[(size_t)Hn * Edim * DHd];
__device__ __align__(256) ushort_t g_Wkl[(size_t)Hn * Edim * DHd];
__device__ __align__(256) ushort_t g_Wvh[(size_t)Hn * Edim * DHd];
__device__ __align__(256) ushort_t g_Wvl[(size_t)Hn * Edim * DHd];
__device__ __align__(256) ushort_t g_Woh[(size_t)Adim * Edim];
__device__ __align__(256) ushort_t g_Wol[(size_t)Adim * Edim];

// ---- mma.sync helpers --------------------------------------------------
__device__ __forceinline__ void ldsm_x4(unsigned* r, const void* p) {
    unsigned addr = (unsigned)__cvta_generic_to_shared(p);
    asm volatile("ldmatrix.sync.aligned.m8n8.x4.shared.b16 {%0,%1,%2,%3}, [%4];"
        : "=r"(r[0]), "=r"(r[1]), "=r"(r[2]), "=r"(r[3]) : "r"(addr));
}
__device__ __forceinline__ void ldsm_x4_t(unsigned* r, const void* p) {
    unsigned addr = (unsigned)__cvta_generic_to_shared(p);
    asm volatile("ldmatrix.sync.aligned.m8n8.x4.trans.shared.b16 {%0,%1,%2,%3}, [%4];"
        : "=r"(r[0]), "=r"(r[1]), "=r"(r[2]), "=r"(r[3]) : "r"(addr));
}
__device__ __forceinline__ void mma_bf16(float* c, const unsigned* a, const unsigned* b) {
    asm volatile("mma.sync.aligned.m16n8k16.row.col.f32.bf16.bf16.f32 "
        "{%0,%1,%2,%3}, {%4,%5,%6,%7}, {%8,%9}, {%0,%1,%2,%3};"
        : "+f"(c[0]), "+f"(c[1]), "+f"(c[2]), "+f"(c[3])
        : "r"(a[0]), "r"(a[1]), "r"(a[2]), "r"(a[3]), "r"(b[0]), "r"(b[1]));
}
__device__ __forceinline__ void cvt_hilo(float x, ushort_t& h, ushort_t& l) {
    __nv_bfloat16 bh = __float2bfloat16(x);
    float rem = x - __bfloat162float(bh);
    __nv_bfloat16 bl = __float2bfloat16(rem);
    h = __bfloat16_as_ushort(bh);
    l = __bfloat16_as_ushort(bl);
}
__device__ __forceinline__ unsigned pk(ushort_t a, ushort_t b) {
    return (unsigned)a | ((unsigned)b << 16);
}
__device__ __forceinline__ void hilo_pair(float x, float y, unsigned& h, unsigned& l) {
    ushort_t hx, lx, hy, ly;
    cvt_hilo(x, hx, lx);
    cvt_hilo(y, hy, ly);
    h = pk(hx, hy);
    l = pk(lx, ly);
}
__device__ __forceinline__ float ex2f(float x) {
    float y; asm("ex2.approx.ftz.f32 %0, %1;" : "=f"(y) : "f"(x)); return y;
}

// ---------------------------------------------------------------------------
// Kernel 0: split fp32 -> bf16 hi/lo (one pass, reused by all GEMMs)
// ---------------------------------------------------------------------------
__global__ __launch_bounds__(256) void split_kernel(
    const float* __restrict__ src, ushort_t* __restrict__ dh,
    ushort_t* __restrict__ dl, int n4)
{
    int i = blockIdx.x * blockDim.x + threadIdx.x;
    if (i >= n4) return;
    float4 v = *(const float4*)(src + (size_t)i * 4);
    ushort_t h0, l0, h1, l1, h2, l2, h3, l3;
    cvt_hilo(v.x, h0, l0); cvt_hilo(v.y, h1, l1);
    cvt_hilo(v.z, h2, l2); cvt_hilo(v.w, h3, l3);
    *(uint2*)(dh + (size_t)i * 4) = make_uint2(pk(h0, h1), pk(h2, h3));
    *(uint2*)(dl + (size_t)i * 4) = make_uint2(pk(l0, l1), pk(l2, l3));
}

// ---------------------------------------------------------------------------
// Kernel 1: fused QKV projection on pre-split bf16 hi/lo inputs.
// Q written fp32; K/V written hi/lo bf16 for direct attn staging.
// ---------------------------------------------------------------------------
__global__ __launch_bounds__(256) void qkv_kernel(
    const float* __restrict__ bq, const float* __restrict__ bk,
    const float* __restrict__ bv)
{
    __shared__ ushort_t As_h[2][128][24];
    __shared__ ushort_t As_l[2][128][24];
    __shared__ ushort_t Bs_h[2][16][136];
    __shared__ ushort_t Bs_l[2][16][136];

    const int tid = threadIdx.x;
    const int lane = tid & 31;
    const int warp = tid >> 5;
    const int wm = warp & 1;
    const int wn = warp >> 1;
    const int m0 = blockIdx.x * 128;
    const int n0 = blockIdx.y * 128;
    const int z = n0 >> 10;
    const ushort_t* Wh   = (z == 0 ? g_Wqh : (z == 1 ? g_Wkh : g_Wvh));
    const ushort_t* Wl   = (z == 0 ? g_Wql : (z == 1 ? g_Wkl : g_Wvl));
    const float* bias    = (z == 0 ? bq : (z == 1 ? bk : bv));

    const int arow = tid >> 1;
    const int apart = (tid & 1) * 8;
    const ushort_t* Agh = g_xh + (size_t)(m0 + arow) * Edim + apart;
    const ushort_t* Agl = g_xl + (size_t)(m0 + arow) * Edim + apart;
    const int bkr = tid >> 4;
    const int bj = (tid & 15) * 8;
    const int cB = n0 + bj;
    const size_t woff = (size_t)((cB >> 6) & 15) * (Edim * DHd) + (cB & 63);
    const ushort_t* Bgh = Wh + woff;
    const ushort_t* Bgl = Wl + woff;

    float C[4][4][4];
#pragma unroll
    for (int i = 0; i < 4; i++)
#pragma unroll
        for (int j = 0; j < 4; j++)
#pragma unroll
            for (int e = 0; e < 4; e++) C[i][j][e] = 0.f;

    uint4 aH, aL, bH, bL;
    aH = *(const uint4*)(Agh);
    aL = *(const uint4*)(Agl);
    bH = *(const uint4*)(Bgh + (size_t)bkr * DHd);
    bL = *(const uint4*)(Bgl + (size_t)bkr * DHd);
    *(uint4*)&As_h[0][arow][apart] = aH;
    *(uint4*)&As_l[0][arow][apart] = aL;
    *(uint4*)&Bs_h[0][bkr][bj] = bH;
    *(uint4*)&Bs_l[0][bkr][bj] = bL;
    __syncthreads();

    const int lrow = lane & 15;
    const int lkoff = (lane >> 4) * 8;

    int buf = 0;
    for (int k0 = 0; k0 < Edim; k0 += 16) {
        const bool more = (k0 + 16) < Edim;
        if (more) {
            aH = *(const uint4*)(Agh + k0 + 16);
            aL = *(const uint4*)(Agl + k0 + 16);
            bH = *(const uint4*)(Bgh + (size_t)(k0 + 16 + bkr) * DHd);
            bL = *(const uint4*)(Bgl + (size_t)(k0 + 16 + bkr) * DHd);
        }

        unsigned a_hi[4][4], a_lo[4][4], b_hi[4][2], b_lo[4][2];
#pragma unroll
        for (int mi = 0; mi < 4; mi++) {
            ldsm_x4(a_hi[mi], &As_h[buf][wm * 64 + mi * 16 + lrow][lkoff]);
            ldsm_x4(a_lo[mi], &As_l[buf][wm * 64 + mi * 16 + lrow][lkoff]);
        }
#pragma unroll
        for (int np = 0; np < 2; np++) {
            unsigned r[4];
            ldsm_x4_t(r, &Bs_h[buf][lrow][wn * 32 + np * 16 + lkoff]);
            b_hi[2*np][0] = r[0]; b_hi[2*np][1] = r[1];
            b_hi[2*np+1][0] = r[2]; b_hi[2*np+1][1] = r[3];
            ldsm_x4_t(r, &Bs_l[buf][lrow][wn * 32 + np * 16 + lkoff]);
            b_lo[2*np][0] = r[0]; b_lo[2*np][1] = r[1];
            b_lo[2*np+1][0] = r[2]; b_lo[2*np+1][1] = r[3];
        }
#pragma unroll
        for (int mi = 0; mi < 4; mi++)
#pragma unroll
            for (int ni = 0; ni < 4; ni++) {
                mma_bf16(C[mi][ni], a_hi[mi], b_hi[ni]);
                mma_bf16(C[mi][ni], a_hi[mi], b_lo[ni]);
                mma_bf16(C[mi][ni], a_lo[mi], b_hi[ni]);
            }

        if (more) {
            int nb = buf ^ 1;
            *(uint4*)&As_h[nb][arow][apart] = aH;
            *(uint4*)&As_l[nb][arow][apart] = aL;
            *(uint4*)&Bs_h[nb][bkr][bj] = bH;
            *(uint4*)&Bs_l[nb][bkr][bj] = bL;
        }
        __syncthreads();
        buf ^= 1;
    }

    // epilogue
#pragma unroll
    for (int mi = 0; mi < 4; mi++)
#pragma unroll
        for (int ni = 0; ni < 4; ni++) {
            int gm = m0 + wm * 64 + mi * 16 + (lane >> 2);
            int gc = n0 + wn * 32 + ni * 8 + (lane & 3) * 2;
            float b0f = bias[gc & 1023];
            float b1f = bias[(gc & 1023) + 1];
            int h = (gc >> 6) & 15;
            int d = gc & 63;
            int bb = gm >> 11, s = gm & (Sdim - 1);
            size_t off0 = ((size_t)(bb * Hn + h) * Sdim + s) * DHd + d;
            int gm2 = gm + 8;
            int bb2 = gm2 >> 11, s2 = gm2 & (Sdim - 1);
            size_t off1 = ((size_t)(bb2 * Hn + h) * Sdim + s2) * DHd + d;
            float v00 = C[mi][ni][0] + b0f, v01 = C[mi][ni][1] + b1f;
            float v10 = C[mi][ni][2] + b0f, v11 = C[mi][ni][3] + b1f;
            if (z == 0) {
                *(float2*)(g_Q + off0) = make_float2(v00, v01);
                *(float2*)(g_Q + off1) = make_float2(v10, v11);
            } else {
                ushort_t* dh = (z == 1 ? g_Kh : g_Vh);
                ushort_t* dl = (z == 1 ? g_Kl : g_Vl);
                unsigned hh, ll;
                hilo_pair(v00, v01, hh, ll);
                *(unsigned*)(dh + off0) = hh;
                *(unsigned*)(dl + off0) = ll;
                hilo_pair(v10, v11, hh, ll);
                *(unsigned*)(dh + off1) = hh;
                *(unsigned*)(dl + off1) = ll;
            }
        }
}

// ---------------------------------------------------------------------------
// Kernel 2: flash attention on tensor cores; K/V pre-split -> staging is a
// pure copy. grid = (S/128, B*H), block = 256 (8 warps x 16 q-rows).
// ---------------------------------------------------------------------------
__global__ __launch_bounds__(256) void attn_kernel()
{
    __shared__ ushort_t Ks_h[64][72];
    __shared__ ushort_t Ks_l[64][72];
    __shared__ ushort_t Vs_h[64][72];
    __shared__ ushort_t Vs_l[64][72];

    const int bh = blockIdx.y;
    const int tid = threadIdx.x;
    const int lane = tid & 31;
    const int warp = tid >> 5;

    const float* Qp = g_Q + (size_t)bh * Sdim * DHd;
    const ushort_t* Khp = g_Kh + (size_t)bh * Sdim * DHd;
    const ushort_t* Klp = g_Kl + (size_t)bh * Sdim * DHd;
    const ushort_t* Vhp = g_Vh + (size_t)bh * Sdim * DHd;
    const ushort_t* Vlp = g_Vl + (size_t)bh * Sdim * DHd;

    const float SCALE = 0.125f * 1.4426950408889634f;

    unsigned aq_h[4][4], aq_l[4][4];
    {
        const int r0 = blockIdx.x * 128 + warp * 16 + (lane >> 2);
        const int r1 = r0 + 8;
        const int cb = (lane & 3) * 2;
#pragma unroll
        for (int kk = 0; kk < 4; kk++) {
            float2 v00 = *(const float2*)(Qp + (size_t)r0 * DHd + kk * 16 + cb);
            float2 v01 = *(const float2*)(Qp + (size_t)r0 * DHd + kk * 16 + cb + 8);
            float2 v10 = *(const float2*)(Qp + (size_t)r1 * DHd + kk * 16 + cb);
            float2 v11 = *(const float2*)(Qp + (size_t)r1 * DHd + kk * 16 + cb + 8);
            hilo_pair(v00.x * SCALE, v00.y * SCALE, aq_h[kk][0], aq_l[kk][0]);
            hilo_pair(v10.x * SCALE, v10.y * SCALE, aq_h[kk][1], aq_l[kk][1]);
            hilo_pair(v01.x * SCALE, v01.y * SCALE, aq_h[kk][2], aq_l[kk][2]);
            hilo_pair(v11.x * SCALE, v11.y * SCALE, aq_h[kk][3], aq_l[kk][3]);
        }
    }

    float o[8][4];
#pragma unroll
    for (int i = 0; i < 8; i++)
#pragma unroll
        for (int e = 0; e < 4; e++) o[i][e] = 0.f;
    float m0_ = -INFINITY, m1_ = -INFINITY, l0_ = 0.f, l1_ = 0.f;

    const int l15 = lane & 15;
    const int lk8 = (lane >> 4) * 8;
    const int srow = tid >> 3;            // staging row 0..31 (+32 on 2nd iter)
    const int sc8 = (tid & 7) * 8;        // staging col group

    for (int t0 = 0; t0 < Sdim; t0 += 64) {
        __syncthreads();
        // pure-copy staging: 8 x 16B per thread
#pragma unroll
        for (int i = 0; i < 2; i++) {
            int row = srow + i * 32;
            size_t goff = (size_t)(t0 + row) * DHd + sc8;
            *(uint4*)&Ks_h[row][sc8] = *(const uint4*)(Khp + goff);
            *(uint4*)&Ks_l[row][sc8] = *(const uint4*)(Klp + goff);
            *(uint4*)&Vs_h[row][sc8] = *(const uint4*)(Vhp + goff);
            *(uint4*)&Vs_l[row][sc8] = *(const uint4*)(Vlp + goff);
        }
        __syncthreads();

        float sc[8][4];
#pragma unroll
        for (int i = 0; i < 8; i++)
#pragma unroll
            for (int e = 0; e < 4; e++) sc[i][e] = 0.f;

#pragma unroll
        for (int kk = 0; kk < 4; kk++) {
#pragma unroll
            for (int pp = 0; pp < 4; pp++) {
                unsigned rh[4], rl[4];
                ldsm_x4(rh, &Ks_h[pp * 16 + l15][kk * 16 + lk8]);
                ldsm_x4(rl, &Ks_l[pp * 16 + l15][kk * 16 + lk8]);
                unsigned bh0[2] = {rh[0], rh[2]}, bh1[2] = {rh[1], rh[3]};
                unsigned bl0[2] = {rl[0], rl[2]}, bl1[2] = {rl[1], rl[3]};
                mma_bf16(sc[2*pp],   aq_h[kk], bh0);
                mma_bf16(sc[2*pp],   aq_h[kk], bl0);
                mma_bf16(sc[2*pp],   aq_l[kk], bh0);
                mma_bf16(sc[2*pp+1], aq_h[kk], bh1);
                mma_bf16(sc[2*pp+1], aq_h[kk], bl1);
                mma_bf16(sc[2*pp+1], aq_l[kk], bh1);
            }
        }

        float mx0 = m0_, mx1 = m1_;
#pragma unroll
        for (int i = 0; i < 8; i++) {
            mx0 = fmaxf(mx0, fmaxf(sc[i][0], sc[i][1]));
            mx1 = fmaxf(mx1, fmaxf(sc[i][2], sc[i][3]));
        }
        mx0 = fmaxf(mx0, __shfl_xor_sync(0xffffffffu, mx0, 1));
        mx0 = fmaxf(mx0, __shfl_xor_sync(0xffffffffu, mx0, 2));
        mx1 = fmaxf(mx1, __shfl_xor_sync(0xffffffffu, mx1, 1));
        mx1 = fmaxf(mx1, __shfl_xor_sync(0xffffffffu, mx1, 2));
        if (mx0 > m0_) {
            float corr = ex2f(m0_ - mx0);
            m0_ = mx0; l0_ *= corr;
#pragma unroll
            for (int i = 0; i < 8; i++) { o[i][0] *= corr; o[i][1] *= corr; }
        }
        if (mx1 > m1_) {
            float corr = ex2f(m1_ - mx1);
            m1_ = mx1; l1_ *= corr;
#pragma unroll
            for (int i = 0; i < 8; i++) { o[i][2] *= corr; o[i][3] *= corr; }
        }
        float ts0 = 0.f, ts1 = 0.f;
#pragma unroll
        for (int i = 0; i < 8; i++) {
            sc[i][0] = ex2f(sc[i][0] - m0_);
            sc[i][1] = ex2f(sc[i][1] - m0_);
            sc[i][2] = ex2f(sc[i][2] - m1_);
            sc[i][3] = ex2f(sc[i][3] - m1_);
            ts0 += sc[i][0] + sc[i][1];
            ts1 += sc[i][2] + sc[i][3];
        }
        ts0 += __shfl_xor_sync(0xffffffffu, ts0, 1);
        ts0 += __shfl_xor_sync(0xffffffffu, ts0, 2);
        ts1 += __shfl_xor_sync(0xffffffffu, ts1, 1);
        ts1 += __shfl_xor_sync(0xffffffffu, ts1, 2);
        l0_ += ts0; l1_ += ts1;

#pragma unroll
        for (int ss = 0; ss < 4; ss++) {
            unsigned ap_h[4], ap_l[4];
            hilo_pair(sc[2*ss][0],   sc[2*ss][1],   ap_h[0], ap_l[0]);
            hilo_pair(sc[2*ss][2],   sc[2*ss][3],   ap_h[1], ap_l[1]);
            hilo_pair(sc[2*ss+1][0], sc[2*ss+1][1], ap_h[2], ap_l[2]);
            hilo_pair(sc[2*ss+1][2], sc[2*ss+1][3], ap_h[3], ap_l[3]);
#pragma unroll
            for (int np = 0; np < 4; np++) {
                unsigned vh[4], vl[4];
                ldsm_x4_t(vh, &Vs_h[ss * 16 + l15][np * 16 + lk8]);
                ldsm_x4_t(vl, &Vs_l[ss * 16 + l15][np * 16 + lk8]);
                unsigned bh0[2] = {vh[0], vh[1]}, bh1[2] = {vh[2], vh[3]};
                unsigned bl0[2] = {vl[0], vl[1]}, bl1[2] = {vl[2], vl[3]};
                mma_bf16(o[2*np],   ap_h, bh0);
                mma_bf16(o[2*np],   ap_h, bl0);
                mma_bf16(o[2*np],   ap_l, bh0);
                mma_bf16(o[2*np+1], ap_h, bh1);
                mma_bf16(o[2*np+1], ap_h, bl1);
                mma_bf16(o[2*np+1], ap_l, bh1);
            }
        }
    }

    // write O as hi/lo bf16 for outproj
    const float inv0 = 1.0f / l0_, inv1 = 1.0f / l1_;
    const int b = bh >> 4, h = bh & 15;
    const int r0 = blockIdx.x * 128 + warp * 16 + (lane >> 2);
    size_t base0 = (size_t)(b * Sdim + r0) * Adim + h * DHd;
    size_t base1 = (size_t)(b * Sdim + r0 + 8) * Adim + h * DHd;
#pragma unroll
    for (int np = 0; np < 8; np++) {
        int col = np * 8 + (lane & 3) * 2;
        unsigned hh, ll;
        hilo_pair(o[np][0] * inv0, o[np][1] * inv0, hh, ll);
        *(unsigned*)(g_Oh + base0 + col) = hh;
        *(unsigned*)(g_Ol + base0 + col) = ll;
        hilo_pair(o[np][2] * inv1, o[np][3] * inv1, hh, ll);
        *(unsigned*)(g_Oh + base1 + col) = hh;
        *(unsigned*)(g_Ol + base1 + col) = ll;
    }
}

// ---------------------------------------------------------------------------
// Kernel 3: output projection on pre-split hi/lo inputs (pure-copy loaders).
// ---------------------------------------------------------------------------
__global__ __launch_bounds__(256) void outproj_kernel(
    const float* __restrict__ bo, float* __restrict__ out)
{
    __shared__ ushort_t As_h[2][128][24];
    __shared__ ushort_t As_l[2][128][24];
    __shared__ ushort_t Bs_h[2][16][136];
    __shared__ ushort_t Bs_l[2][16][136];

    const int tid = threadIdx.x;
    const int lane = tid & 31;
    const int warp = tid >> 5;
    const int wm = warp & 1;
    const int wn = warp >> 1;
    const int m0 = blockIdx.x * 128;
    const int n0 = blockIdx.y * 128;

    const int arow = tid >> 1;
    const int apart = (tid & 1) * 8;
    const ushort_t* Agh = g_Oh + (size_t)(m0 + arow) * Adim + apart;
    const ushort_t* Agl = g_Ol + (size_t)(m0 + arow) * Adim + apart;
    const int bkr = tid >> 4;
    const int bj = (tid & 15) * 8;
    const ushort_t* Bgh = g_Woh + n0 + bj;
    const ushort_t* Bgl = g_Wol + n0 + bj;

    float C[4][4][4];
#pragma unroll
    for (int i = 0; i < 4; i++)
#pragma unroll
        for (int j = 0; j < 4; j++)
#pragma unroll
            for (int e = 0; e < 4; e++) C[i][j][e] = 0.f;

    uint4 aH, aL, bH, bL;
    aH = *(const uint4*)(Agh);
    aL = *(const uint4*)(Agl);
    bH = *(const uint4*)(Bgh + (size_t)bkr * Edim);
    bL = *(const uint4*)(Bgl + (size_t)bkr * Edim);
    *(uint4*)&As_h[0][arow][apart] = aH;
    *(uint4*)&As_l[0][arow][apart] = aL;
    *(uint4*)&Bs_h[0][bkr][bj] = bH;
    *(uint4*)&Bs_l[0][bkr][bj] = bL;
    __syncthreads();

    const int lrow = lane & 15;
    const int lkoff = (lane >> 4) * 8;

    int buf = 0;
    for (int k0 = 0; k0 < Adim; k0 += 16) {
        const bool more = (k0 + 16) < Adim;
        if (more) {
            aH = *(const uint4*)(Agh + k0 + 16);
            aL = *(const uint4*)(Agl + k0 + 16);
            bH = *(const uint4*)(Bgh + (size_t)(k0 + 16 + bkr) * Edim);
            bL = *(const uint4*)(Bgl + (size_t)(k0 + 16 + bkr) * Edim);
        }

        unsigned a_hi[4][4], a_lo[4][4], b_hi[4][2], b_lo[4][2];
#pragma unroll
        for (int mi = 0; mi < 4; mi++) {
            ldsm_x4(a_hi[mi], &As_h[buf][wm * 64 + mi * 16 + lrow][lkoff]);
            ldsm_x4(a_lo[mi], &As_l[buf][wm * 64 + mi * 16 + lrow][lkoff]);
        }
#pragma unroll
        for (int np = 0; np < 2; np++) {
            unsigned r[4];
            ldsm_x4_t(r, &Bs_h[buf][lrow][wn * 32 + np * 16 + lkoff]);
            b_hi[2*np][0] = r[0]; b_hi[2*np][1] = r[1];
            b_hi[2*np+1][0] = r[2]; b_hi[2*np+1][1] = r[3];
            ldsm_x4_t(r, &Bs_l[buf][lrow][wn * 32 + np * 16 + lkoff]);
            b_lo[2*np][0] = r[0]; b_lo[2*np][1] = r[1];
            b_lo[2*np+1][0] = r[2]; b_lo[2*np+1][1] = r[3];
        }
#pragma unroll
        for (int mi = 0; mi < 4; mi++)
#pragma unroll
            for (int ni = 0; ni < 4; ni++) {
                mma_bf16(C[mi][ni], a_hi[mi], b_hi[ni]);
                mma_bf16(C[mi][ni], a_hi[mi], b_lo[ni]);
                mma_bf16(C[mi][ni], a_lo[mi], b_hi[ni]);
            }

        if (more) {
            int nb = buf ^ 1;
            *(uint4*)&As_h[nb][arow][apart] = aH;
            *(uint4*)&As_l[nb][arow][apart] = aL;
            *(uint4*)&Bs_h[nb][bkr][bj] = bH;
            *(uint4*)&Bs_l[nb][bkr][bj] = bL;
        }
        __syncthreads();
        buf ^= 1;
    }

#pragma unroll
    for (int mi = 0; mi < 4; mi++)
#pragma unroll
        for (int ni = 0; ni < 4; ni++) {
            int gm = m0 + wm * 64 + mi * 16 + (lane >> 2);
            int gc = n0 + wn * 32 + ni * 8 + (lane & 3) * 2;
            float b0f = bo[gc], b1f = bo[gc + 1];
            float* p0 = out + (size_t)gm * Edim + gc;
            *(float2*)p0 = make_float2(C[mi][ni][0] + b0f, C[mi][ni][1] + b1f);
            float* p1 = out + (size_t)(gm + 8) * Edim + gc;
            *(float2*)p1 = make_float2(C[mi][ni][2] + b0f, C[mi][ni][3] + b1f);
        }
}

extern "C" void kernel_launch(void* const* d_in, const int* in_sizes, int n_in,
                              void* d_out, int out_size)
{
    const float* x  = (const float*)d_in[0];
    const float* Wq = (const float*)d_in[1];
    const float* bq = (const float*)d_in[2];
    const float* Wk = (const float*)d_in[3];
    const float* bk = (const float*)d_in[4];
    const float* Wv = (const float*)d_in[5];
    const float* bv = (const float*)d_in[6];
    const float* Wo = (const float*)d_in[7];
    const float* bo = (const float*)d_in[8];
    float* out = (float*)d_out;

    ushort_t *xh, *xl, *wqh, *wql, *wkh, *wkl, *wvh, *wvl, *woh, *wol;
    cudaGetSymbolAddress((void**)&xh,  g_xh);  cudaGetSymbolAddress((void**)&xl,  g_xl);
    cudaGetSymbolAddress((void**)&wqh, g_Wqh); cudaGetSymbolAddress((void**)&wql, g_Wql);
    cudaGetSymbolAddress((void**)&wkh, g_Wkh); cudaGetSymbolAddress((void**)&wkl, g_Wkl);
    cudaGetSymbolAddress((void**)&wvh, g_Wvh); cudaGetSymbolAddress((void**)&wvl, g_Wvl);
    cudaGetSymbolAddress((void**)&woh, g_Woh); cudaGetSymbolAddress((void**)&wol, g_Wol);

    const int nX = Mrows * Edim / 4;          // 1,048,576
    const int nW = Hn * Edim * DHd / 4;       // 262,144
    split_kernel<<<(nX + 255) / 256, 256>>>(x,  xh,  xl,  nX);
    split_kernel<<<(nW + 255) / 256, 256>>>(Wq, wqh, wql, nW);
    split_kernel<<<(nW + 255) / 256, 256>>>(Wk, wkh, wkl, nW);
    split_kernel<<<(nW + 255) / 256, 256>>>(Wv, wvh, wvl, nW);
    split_kernel<<<(nW + 255) / 256, 256>>>(Wo, woh, wol, nW);

    dim3 g1(Mrows / 128, (3 * Hn * DHd) / 128);   // (32, 24)
    qkv_kernel<<<g1, 256>>>(bq, bk, bv);

    dim3 g2(Sdim / 128, Bsz * Hn);                // (16, 32)
    attn_kernel<<<g2, 256>>>();

    dim3 g3(Mrows / 128, Edim / 128);             // (32, 8)
    outproj_kernel<<<g3, 256>>>(bo, out);
}

// round 9
// speedup vs baseline: 1.1457x; 1.1457x over previous
#include <cuda_runtime.h>
#include <cuda_bf16.h>
#include <math.h>

#define Bsz 2
#define Sdim 2048
#define Edim 1024
#define Hn 16
#define DHd 64
#define Adim 1024
#define Mrows (Bsz * Sdim)  // 4096

typedef unsigned short ushort_t;

// Scratch (allocation-free rule: __device__ globals)
__device__ __align__(256) float    g_Q [(size_t)Bsz * Hn * Sdim * DHd];  // [B,H,S,DH]
__device__ __align__(256) ushort_t g_Kh[(size_t)Bsz * Hn * Sdim * DHd];  // K hi bf16
__device__ __align__(256) ushort_t g_Kl[(size_t)Bsz * Hn * Sdim * DHd];  // K lo bf16
__device__ __align__(256) ushort_t g_Vh[(size_t)Bsz * Hn * Sdim * DHd];
__device__ __align__(256) ushort_t g_Vl[(size_t)Bsz * Hn * Sdim * DHd];
__device__ __align__(256) float    g_O [(size_t)Bsz * Sdim * Adim];      // [B,S,A]

// ---- mma.sync helpers --------------------------------------------------
__device__ __forceinline__ void ldsm_x4(unsigned* r, const void* p) {
    unsigned addr = (unsigned)__cvta_generic_to_shared(p);
    asm volatile("ldmatrix.sync.aligned.m8n8.x4.shared.b16 {%0,%1,%2,%3}, [%4];"
        : "=r"(r[0]), "=r"(r[1]), "=r"(r[2]), "=r"(r[3]) : "r"(addr));
}
__device__ __forceinline__ void ldsm_x4_t(unsigned* r, const void* p) {
    unsigned addr = (unsigned)__cvta_generic_to_shared(p);
    asm volatile("ldmatrix.sync.aligned.m8n8.x4.trans.shared.b16 {%0,%1,%2,%3}, [%4];"
        : "=r"(r[0]), "=r"(r[1]), "=r"(r[2]), "=r"(r[3]) : "r"(addr));
}
__device__ __forceinline__ void mma_bf16(float* c, const unsigned* a, const unsigned* b) {
    asm volatile("mma.sync.aligned.m16n8k16.row.col.f32.bf16.bf16.f32 "
        "{%0,%1,%2,%3}, {%4,%5,%6,%7}, {%8,%9}, {%0,%1,%2,%3};"
        : "+f"(c[0]), "+f"(c[1]), "+f"(c[2]), "+f"(c[3])
        : "r"(a[0]), "r"(a[1]), "r"(a[2]), "r"(a[3]), "r"(b[0]), "r"(b[1]));
}
__device__ __forceinline__ void cvt_hilo(float x, ushort_t& h, ushort_t& l) {
    __nv_bfloat16 bh = __float2bfloat16(x);
    float rem = x - __bfloat162float(bh);
    __nv_bfloat16 bl = __float2bfloat16(rem);
    h = __bfloat16_as_ushort(bh);
    l = __bfloat16_as_ushort(bl);
}
__device__ __forceinline__ unsigned pk(ushort_t a, ushort_t b) {
    return (unsigned)a | ((unsigned)b << 16);
}
__device__ __forceinline__ void hilo_pair(float x, float y, unsigned& h, unsigned& l) {
    ushort_t hx, lx, hy, ly;
    cvt_hilo(x, hx, lx);
    cvt_hilo(y, hy, ly);
    h = pk(hx, hy);
    l = pk(lx, ly);
}
__device__ __forceinline__ float ex2f(float x) {
    float y; asm("ex2.approx.ftz.f32 %0, %1;" : "=f"(y) : "f"(x)); return y;
}
// ---- cp.async ----
__device__ __forceinline__ void cp_async16(void* smem_dst, const void* gmem_src) {
    unsigned d = (unsigned)__cvta_generic_to_shared(smem_dst);
    asm volatile("cp.async.cg.shared.global [%0], [%1], 16;" :: "r"(d), "l"(gmem_src));
}
__device__ __forceinline__ void cp_commit() {
    asm volatile("cp.async.commit_group;" ::: "memory");
}
__device__ __forceinline__ void cp_wait0() {
    asm volatile("cp.async.wait_group 0;" ::: "memory");
}

// ---------------------------------------------------------------------------
// Kernel 1: fused QKV projection (R6/R7-proven mainloop, fp32 in / convert
// in-kernel). Epilogue: Q written fp32; K/V written as hi/lo bf16.
// ---------------------------------------------------------------------------
__global__ __launch_bounds__(256) void qkv_kernel(
    const float* __restrict__ x,
    const float* __restrict__ Wq, const float* __restrict__ bq,
    const float* __restrict__ Wk, const float* __restrict__ bk,
    const float* __restrict__ Wv, const float* __restrict__ bv)
{
    __shared__ ushort_t As_h[2][128][24];
    __shared__ ushort_t As_l[2][128][24];
    __shared__ ushort_t Bs_h[2][16][136];
    __shared__ ushort_t Bs_l[2][16][136];

    const int tid = threadIdx.x;
    const int lane = tid & 31;
    const int warp = tid >> 5;
    const int wm = warp & 1;
    const int wn = warp >> 1;
    const int m0 = blockIdx.x * 128;
    const int n0 = blockIdx.y * 128;
    const int z = n0 >> 10;
    const float* W    = (z == 0 ? Wq : (z == 1 ? Wk : Wv));
    const float* bias = (z == 0 ? bq : (z == 1 ? bk : bv));

    const int arow = tid >> 1;
    const int apart = (tid & 1) * 8;
    const float* Ag = x + (size_t)(m0 + arow) * Edim + apart;
    const int bkr = tid >> 4;
    const int bj = (tid & 15) * 8;
    const int cB = n0 + bj;
    const float* Bg = W + (size_t)((cB >> 6) & 15) * (Edim * DHd) + (cB & 63);

    float C[4][4][4];
#pragma unroll
    for (int i = 0; i < 4; i++)
#pragma unroll
        for (int j = 0; j < 4; j++)
#pragma unroll
            for (int e = 0; e < 4; e++) C[i][j][e] = 0.f;

    float4 a0r, a1r, b0r, b1r;
    a0r = *(const float4*)(Ag);
    a1r = *(const float4*)(Ag + 4);
    b0r = *(const float4*)(Bg + (size_t)bkr * DHd);
    b1r = *(const float4*)(Bg + (size_t)bkr * DHd + 4);
    {
        float av[8] = {a0r.x, a0r.y, a0r.z, a0r.w, a1r.x, a1r.y, a1r.z, a1r.w};
        float bw[8] = {b0r.x, b0r.y, b0r.z, b0r.w, b1r.x, b1r.y, b1r.z, b1r.w};
        ushort_t ah[8], al[8], bh[8], bl[8];
#pragma unroll
        for (int j = 0; j < 8; j++) { cvt_hilo(av[j], ah[j], al[j]); cvt_hilo(bw[j], bh[j], bl[j]); }
        *(uint4*)&As_h[0][arow][apart] = make_uint4(pk(ah[0],ah[1]), pk(ah[2],ah[3]), pk(ah[4],ah[5]), pk(ah[6],ah[7]));
        *(uint4*)&As_l[0][arow][apart] = make_uint4(pk(al[0],al[1]), pk(al[2],al[3]), pk(al[4],al[5]), pk(al[6],al[7]));
        *(uint4*)&Bs_h[0][bkr][bj]     = make_uint4(pk(bh[0],bh[1]), pk(bh[2],bh[3]), pk(bh[4],bh[5]), pk(bh[6],bh[7]));
        *(uint4*)&Bs_l[0][bkr][bj]     = make_uint4(pk(bl[0],bl[1]), pk(bl[2],bl[3]), pk(bl[4],bl[5]), pk(bl[6],bl[7]));
    }
    __syncthreads();

    const int lrow = lane & 15;
    const int lkoff = (lane >> 4) * 8;

    int buf = 0;
    for (int k0 = 0; k0 < Edim; k0 += 16) {
        const bool more = (k0 + 16) < Edim;
        if (more) {
            a0r = *(const float4*)(Ag + k0 + 16);
            a1r = *(const float4*)(Ag + k0 + 20);
            b0r = *(const float4*)(Bg + (size_t)(k0 + 16 + bkr) * DHd);
            b1r = *(const float4*)(Bg + (size_t)(k0 + 16 + bkr) * DHd + 4);
        }

        unsigned a_hi[4][4], a_lo[4][4], b_hi[4][2], b_lo[4][2];
#pragma unroll
        for (int mi = 0; mi < 4; mi++) {
            ldsm_x4(a_hi[mi], &As_h[buf][wm * 64 + mi * 16 + lrow][lkoff]);
            ldsm_x4(a_lo[mi], &As_l[buf][wm * 64 + mi * 16 + lrow][lkoff]);
        }
#pragma unroll
        for (int np = 0; np < 2; np++) {
            unsigned r[4];
            ldsm_x4_t(r, &Bs_h[buf][lrow][wn * 32 + np * 16 + lkoff]);
            b_hi[2*np][0] = r[0]; b_hi[2*np][1] = r[1];
            b_hi[2*np+1][0] = r[2]; b_hi[2*np+1][1] = r[3];
            ldsm_x4_t(r, &Bs_l[buf][lrow][wn * 32 + np * 16 + lkoff]);
            b_lo[2*np][0] = r[0]; b_lo[2*np][1] = r[1];
            b_lo[2*np+1][0] = r[2]; b_lo[2*np+1][1] = r[3];
        }
#pragma unroll
        for (int mi = 0; mi < 4; mi++)
#pragma unroll
            for (int ni = 0; ni < 4; ni++) {
                mma_bf16(C[mi][ni], a_hi[mi], b_hi[ni]);
                mma_bf16(C[mi][ni], a_hi[mi], b_lo[ni]);
                mma_bf16(C[mi][ni], a_lo[mi], b_hi[ni]);
            }

        if (more) {
            int nb = buf ^ 1;
            float av[8] = {a0r.x, a0r.y, a0r.z, a0r.w, a1r.x, a1r.y, a1r.z, a1r.w};
            float bw[8] = {b0r.x, b0r.y, b0r.z, b0r.w, b1r.x, b1r.y, b1r.z, b1r.w};
            ushort_t ah[8], al[8], bh[8], bl[8];
#pragma unroll
            for (int j = 0; j < 8; j++) { cvt_hilo(av[j], ah[j], al[j]); cvt_hilo(bw[j], bh[j], bl[j]); }
            *(uint4*)&As_h[nb][arow][apart] = make_uint4(pk(ah[0],ah[1]), pk(ah[2],ah[3]), pk(ah[4],ah[5]), pk(ah[6],ah[7]));
            *(uint4*)&As_l[nb][arow][apart] = make_uint4(pk(al[0],al[1]), pk(al[2],al[3]), pk(al[4],al[5]), pk(al[6],al[7]));
            *(uint4*)&Bs_h[nb][bkr][bj]     = make_uint4(pk(bh[0],bh[1]), pk(bh[2],bh[3]), pk(bh[4],bh[5]), pk(bh[6],bh[7]));
            *(uint4*)&Bs_l[nb][bkr][bj]     = make_uint4(pk(bl[0],bl[1]), pk(bl[2],bl[3]), pk(bl[4],bl[5]), pk(bl[6],bl[7]));
        }
        __syncthreads();
        buf ^= 1;
    }

    // epilogue: Q fp32; K/V hi/lo bf16
#pragma unroll
    for (int mi = 0; mi < 4; mi++)
#pragma unroll
        for (int ni = 0; ni < 4; ni++) {
            int gm = m0 + wm * 64 + mi * 16 + (lane >> 2);
            int gc = n0 + wn * 32 + ni * 8 + (lane & 3) * 2;
            float b0f = bias[gc & 1023];
            float b1f = bias[(gc & 1023) + 1];
            int h = (gc >> 6) & 15;
            int d = gc & 63;
            int bb = gm >> 11, s = gm & (Sdim - 1);
            size_t off0 = ((size_t)(bb * Hn + h) * Sdim + s) * DHd + d;
            int gm2 = gm + 8;
            int bb2 = gm2 >> 11, s2 = gm2 & (Sdim - 1);
            size_t off1 = ((size_t)(bb2 * Hn + h) * Sdim + s2) * DHd + d;
            float v00 = C[mi][ni][0] + b0f, v01 = C[mi][ni][1] + b1f;
            float v10 = C[mi][ni][2] + b0f, v11 = C[mi][ni][3] + b1f;
            if (z == 0) {
                *(float2*)(g_Q + off0) = make_float2(v00, v01);
                *(float2*)(g_Q + off1) = make_float2(v10, v11);
            } else {
                ushort_t* dh = (z == 1 ? g_Kh : g_Vh);
                ushort_t* dl = (z == 1 ? g_Kl : g_Vl);
                unsigned hh, ll;
                hilo_pair(v00, v01, hh, ll);
                *(unsigned*)(dh + off0) = hh;
                *(unsigned*)(dl + off0) = ll;
                hilo_pair(v10, v11, hh, ll);
                *(unsigned*)(dh + off1) = hh;
                *(unsigned*)(dl + off1) = ll;
            }
        }
}

// ---------------------------------------------------------------------------
// Kernel 2: flash attention; K/V pre-split -> cp.async double-buffered
// pure-copy staging. grid = (S/128, B*H), block = 256 (8 warps x 16 q-rows).
// Dynamic smem: 2 bufs x 4 arrays x 64x72 ushorts = 73,728 B.
// ---------------------------------------------------------------------------
#define ATILE 4608            // 64*72 ushorts per array
#define ABUF  (4 * ATILE)     // per-buffer stride
#define ATTN_SMEM_BYTES (2 * ABUF * 2)

__global__ __launch_bounds__(256) void attn_kernel()
{
    extern __shared__ ushort_t smem[];

    const int bh = blockIdx.y;
    const int tid = threadIdx.x;
    const int lane = tid & 31;
    const int warp = tid >> 5;

    const float* Qp = g_Q + (size_t)bh * Sdim * DHd;
    const ushort_t* Khp = g_Kh + (size_t)bh * Sdim * DHd;
    const ushort_t* Klp = g_Kl + (size_t)bh * Sdim * DHd;
    const ushort_t* Vhp = g_Vh + (size_t)bh * Sdim * DHd;
    const ushort_t* Vlp = g_Vl + (size_t)bh * Sdim * DHd;

    const float SCALE = 0.125f * 1.4426950408889634f;

    unsigned aq_h[4][4], aq_l[4][4];
    {
        const int r0 = blockIdx.x * 128 + warp * 16 + (lane >> 2);
        const int r1 = r0 + 8;
        const int cb = (lane & 3) * 2;
#pragma unroll
        for (int kk = 0; kk < 4; kk++) {
            float2 v00 = *(const float2*)(Qp + (size_t)r0 * DHd + kk * 16 + cb);
            float2 v01 = *(const float2*)(Qp + (size_t)r0 * DHd + kk * 16 + cb + 8);
            float2 v10 = *(const float2*)(Qp + (size_t)r1 * DHd + kk * 16 + cb);
            float2 v11 = *(const float2*)(Qp + (size_t)r1 * DHd + kk * 16 + cb + 8);
            hilo_pair(v00.x * SCALE, v00.y * SCALE, aq_h[kk][0], aq_l[kk][0]);
            hilo_pair(v10.x * SCALE, v10.y * SCALE, aq_h[kk][1], aq_l[kk][1]);
            hilo_pair(v01.x * SCALE, v01.y * SCALE, aq_h[kk][2], aq_l[kk][2]);
            hilo_pair(v11.x * SCALE, v11.y * SCALE, aq_h[kk][3], aq_l[kk][3]);
        }
    }

    float o[8][4];
#pragma unroll
    for (int i = 0; i < 8; i++)
#pragma unroll
        for (int e = 0; e < 4; e++) o[i][e] = 0.f;
    float m0_ = -INFINITY, m1_ = -INFINITY, l0_ = 0.f, l1_ = 0.f;

    const int l15 = lane & 15;
    const int lk8 = (lane >> 4) * 8;
    const int srow = tid >> 3;           // 0..31 (+32 on 2nd chunk)
    const int sc8 = (tid & 7) * 8;       // 16B column group

    // stage tile 0 into buffer 0
#pragma unroll
    for (int i = 0; i < 2; i++) {
        int row = srow + i * 32;
        size_t goff = (size_t)row * DHd + sc8;
        int soff = row * 72 + sc8;
        cp_async16(&smem[0 * ABUF + 0 * ATILE + soff], Khp + goff);
        cp_async16(&smem[0 * ABUF + 1 * ATILE + soff], Klp + goff);
        cp_async16(&smem[0 * ABUF + 2 * ATILE + soff], Vhp + goff);
        cp_async16(&smem[0 * ABUF + 3 * ATILE + soff], Vlp + goff);
    }
    cp_commit();

    int buf = 0;
    for (int t0 = 0; t0 < Sdim; t0 += 64) {
        cp_wait0();
        __syncthreads();

        const ushort_t* KsH = smem + buf * ABUF + 0 * ATILE;
        const ushort_t* KsL = smem + buf * ABUF + 1 * ATILE;
        const ushort_t* VsH = smem + buf * ABUF + 2 * ATILE;
        const ushort_t* VsL = smem + buf * ABUF + 3 * ATILE;

        // prefetch next tile into other buffer
        if (t0 + 64 < Sdim) {
            int nb = buf ^ 1;
#pragma unroll
            for (int i = 0; i < 2; i++) {
                int row = srow + i * 32;
                size_t goff = (size_t)(t0 + 64 + row) * DHd + sc8;
                int soff = row * 72 + sc8;
                cp_async16(&smem[nb * ABUF + 0 * ATILE + soff], Khp + goff);
                cp_async16(&smem[nb * ABUF + 1 * ATILE + soff], Klp + goff);
                cp_async16(&smem[nb * ABUF + 2 * ATILE + soff], Vhp + goff);
                cp_async16(&smem[nb * ABUF + 3 * ATILE + soff], Vlp + goff);
            }
            cp_commit();
        }

        float sc[8][4];
#pragma unroll
        for (int i = 0; i < 8; i++)
#pragma unroll
            for (int e = 0; e < 4; e++) sc[i][e] = 0.f;

#pragma unroll
        for (int kk = 0; kk < 4; kk++) {
#pragma unroll
            for (int pp = 0; pp < 4; pp++) {
                unsigned rh[4], rl[4];
                ldsm_x4(rh, &KsH[(pp * 16 + l15) * 72 + kk * 16 + lk8]);
                ldsm_x4(rl, &KsL[(pp * 16 + l15) * 72 + kk * 16 + lk8]);
                unsigned bh0[2] = {rh[0], rh[2]}, bh1[2] = {rh[1], rh[3]};
                unsigned bl0[2] = {rl[0], rl[2]}, bl1[2] = {rl[1], rl[3]};
                mma_bf16(sc[2*pp],   aq_h[kk], bh0);
                mma_bf16(sc[2*pp],   aq_h[kk], bl0);
                mma_bf16(sc[2*pp],   aq_l[kk], bh0);
                mma_bf16(sc[2*pp+1], aq_h[kk], bh1);
                mma_bf16(sc[2*pp+1], aq_h[kk], bl1);
                mma_bf16(sc[2*pp+1], aq_l[kk], bh1);
            }
        }

        float mx0 = m0_, mx1 = m1_;
#pragma unroll
        for (int i = 0; i < 8; i++) {
            mx0 = fmaxf(mx0, fmaxf(sc[i][0], sc[i][1]));
            mx1 = fmaxf(mx1, fmaxf(sc[i][2], sc[i][3]));
        }
        mx0 = fmaxf(mx0, __shfl_xor_sync(0xffffffffu, mx0, 1));
        mx0 = fmaxf(mx0, __shfl_xor_sync(0xffffffffu, mx0, 2));
        mx1 = fmaxf(mx1, __shfl_xor_sync(0xffffffffu, mx1, 1));
        mx1 = fmaxf(mx1, __shfl_xor_sync(0xffffffffu, mx1, 2));
        if (mx0 > m0_) {
            float corr = ex2f(m0_ - mx0);
            m0_ = mx0; l0_ *= corr;
#pragma unroll
            for (int i = 0; i < 8; i++) { o[i][0] *= corr; o[i][1] *= corr; }
        }
        if (mx1 > m1_) {
            float corr = ex2f(m1_ - mx1);
            m1_ = mx1; l1_ *= corr;
#pragma unroll
            for (int i = 0; i < 8; i++) { o[i][2] *= corr; o[i][3] *= corr; }
        }
        float ts0 = 0.f, ts1 = 0.f;
#pragma unroll
        for (int i = 0; i < 8; i++) {
            sc[i][0] = ex2f(sc[i][0] - m0_);
            sc[i][1] = ex2f(sc[i][1] - m0_);
            sc[i][2] = ex2f(sc[i][2] - m1_);
            sc[i][3] = ex2f(sc[i][3] - m1_);
            ts0 += sc[i][0] + sc[i][1];
            ts1 += sc[i][2] + sc[i][3];
        }
        ts0 += __shfl_xor_sync(0xffffffffu, ts0, 1);
        ts0 += __shfl_xor_sync(0xffffffffu, ts0, 2);
        ts1 += __shfl_xor_sync(0xffffffffu, ts1, 1);
        ts1 += __shfl_xor_sync(0xffffffffu, ts1, 2);
        l0_ += ts0; l1_ += ts1;

#pragma unroll
        for (int ss = 0; ss < 4; ss++) {
            unsigned ap_h[4], ap_l[4];
            hilo_pair(sc[2*ss][0],   sc[2*ss][1],   ap_h[0], ap_l[0]);
            hilo_pair(sc[2*ss][2],   sc[2*ss][3],   ap_h[1], ap_l[1]);
            hilo_pair(sc[2*ss+1][0], sc[2*ss+1][1], ap_h[2], ap_l[2]);
            hilo_pair(sc[2*ss+1][2], sc[2*ss+1][3], ap_h[3], ap_l[3]);
#pragma unroll
            for (int np = 0; np < 4; np++) {
                unsigned vh[4], vl[4];
                ldsm_x4_t(vh, &VsH[(ss * 16 + l15) * 72 + np * 16 + lk8]);
                ldsm_x4_t(vl, &VsL[(ss * 16 + l15) * 72 + np * 16 + lk8]);
                unsigned bh0[2] = {vh[0], vh[1]}, bh1[2] = {vh[2], vh[3]};
                unsigned bl0[2] = {vl[0], vl[1]}, bl1[2] = {vl[2], vl[3]};
                mma_bf16(o[2*np],   ap_h, bh0);
                mma_bf16(o[2*np],   ap_h, bl0);
                mma_bf16(o[2*np],   ap_l, bh0);
                mma_bf16(o[2*np+1], ap_h, bh1);
                mma_bf16(o[2*np+1], ap_h, bl1);
                mma_bf16(o[2*np+1], ap_l, bh1);
            }
        }
        __syncthreads();   // all reads of buf done before it is refilled next round
        buf ^= 1;
    }

    const float inv0 = 1.0f / l0_, inv1 = 1.0f / l1_;
    const int b = bh >> 4, h = bh & 15;
    const int r0 = blockIdx.x * 128 + warp * 16 + (lane >> 2);
    float* op0 = g_O + (size_t)(b * Sdim + r0) * Adim + h * DHd;
    float* op1 = g_O + (size_t)(b * Sdim + r0 + 8) * Adim + h * DHd;
#pragma unroll
    for (int np = 0; np < 8; np++) {
        int col = np * 8 + (lane & 3) * 2;
        *(float2*)(op0 + col) = make_float2(o[np][0] * inv0, o[np][1] * inv0);
        *(float2*)(op1 + col) = make_float2(o[np][2] * inv1, o[np][3] * inv1);
    }
}

// ---------------------------------------------------------------------------
// Kernel 3: output projection (R6/R7-proven, fp32 in / convert in-kernel).
// ---------------------------------------------------------------------------
__global__ __launch_bounds__(256) void outproj_kernel(
    const float* __restrict__ Wo, const float* __restrict__ bo,
    float* __restrict__ out)
{
    __shared__ ushort_t As_h[2][128][24];
    __shared__ ushort_t As_l[2][128][24];
    __shared__ ushort_t Bs_h[2][16][136];
    __shared__ ushort_t Bs_l[2][16][136];

    const int tid = threadIdx.x;
    const int lane = tid & 31;
    const int warp = tid >> 5;
    const int wm = warp & 1;
    const int wn = warp >> 1;
    const int m0 = blockIdx.x * 128;
    const int n0 = blockIdx.y * 128;

    const int arow = tid >> 1;
    const int apart = (tid & 1) * 8;
    const float* Ag = g_O + (size_t)(m0 + arow) * Adim + apart;
    const int bkr = tid >> 4;
    const int bj = (tid & 15) * 8;
    const float* Bg = Wo + n0 + bj;

    float C[4][4][4];
#pragma unroll
    for (int i = 0; i < 4; i++)
#pragma unroll
        for (int j = 0; j < 4; j++)
#pragma unroll
            for (int e = 0; e < 4; e++) C[i][j][e] = 0.f;

    float4 a0r, a1r, b0r, b1r;
    a0r = *(const float4*)(Ag);
    a1r = *(const float4*)(Ag + 4);
    b0r = *(const float4*)(Bg + (size_t)bkr * Edim);
    b1r = *(const float4*)(Bg + (size_t)bkr * Edim + 4);
    {
        float av[8] = {a0r.x, a0r.y, a0r.z, a0r.w, a1r.x, a1r.y, a1r.z, a1r.w};
        float bw[8] = {b0r.x, b0r.y, b0r.z, b0r.w, b1r.x, b1r.y, b1r.z, b1r.w};
        ushort_t ah[8], al[8], bh[8], bl[8];
#pragma unroll
        for (int j = 0; j < 8; j++) { cvt_hilo(av[j], ah[j], al[j]); cvt_hilo(bw[j], bh[j], bl[j]); }
        *(uint4*)&As_h[0][arow][apart] = make_uint4(pk(ah[0],ah[1]), pk(ah[2],ah[3]), pk(ah[4],ah[5]), pk(ah[6],ah[7]));
        *(uint4*)&As_l[0][arow][apart] = make_uint4(pk(al[0],al[1]), pk(al[2],al[3]), pk(al[4],al[5]), pk(al[6],al[7]));
        *(uint4*)&Bs_h[0][bkr][bj]     = make_uint4(pk(bh[0],bh[1]), pk(bh[2],bh[3]), pk(bh[4],bh[5]), pk(bh[6],bh[7]));
        *(uint4*)&Bs_l[0][bkr][bj]     = make_uint4(pk(bl[0],bl[1]), pk(bl[2],bl[3]), pk(bl[4],bl[5]), pk(bl[6],bl[7]));
    }
    __syncthreads();

    const int lrow = lane & 15;
    const int lkoff = (lane >> 4) * 8;

    int buf = 0;
    for (int k0 = 0; k0 < Adim; k0 += 16) {
        const bool more = (k0 + 16) < Adim;
        if (more) {
            a0r = *(const float4*)(Ag + k0 + 16);
            a1r = *(const float4*)(Ag + k0 + 20);
            b0r = *(const float4*)(Bg + (size_t)(k0 + 16 + bkr) * Edim);
            b1r = *(const float4*)(Bg + (size_t)(k0 + 16 + bkr) * Edim + 4);
        }

        unsigned a_hi[4][4], a_lo[4][4], b_hi[4][2], b_lo[4][2];
#pragma unroll
        for (int mi = 0; mi < 4; mi++) {
            ldsm_x4(a_hi[mi], &As_h[buf][wm * 64 + mi * 16 + lrow][lkoff]);
            ldsm_x4(a_lo[mi], &As_l[buf][wm * 64 + mi * 16 + lrow][lkoff]);
        }
#pragma unroll
        for (int np = 0; np < 2; np++) {
            unsigned r[4];
            ldsm_x4_t(r, &Bs_h[buf][lrow][wn * 32 + np * 16 + lkoff]);
            b_hi[2*np][0] = r[0]; b_hi[2*np][1] = r[1];
            b_hi[2*np+1][0] = r[2]; b_hi[2*np+1][1] = r[3];
            ldsm_x4_t(r, &Bs_l[buf][lrow][wn * 32 + np * 16 + lkoff]);
            b_lo[2*np][0] = r[0]; b_lo[2*np][1] = r[1];
            b_lo[2*np+1][0] = r[2]; b_lo[2*np+1][1] = r[3];
        }
#pragma unroll
        for (int mi = 0; mi < 4; mi++)
#pragma unroll
            for (int ni = 0; ni < 4; ni++) {
                mma_bf16(C[mi][ni], a_hi[mi], b_hi[ni]);
                mma_bf16(C[mi][ni], a_hi[mi], b_lo[ni]);
                mma_bf16(C[mi][ni], a_lo[mi], b_hi[ni]);
            }

        if (more) {
            int nb = buf ^ 1;
            float av[8] = {a0r.x, a0r.y, a0r.z, a0r.w, a1r.x, a1r.y, a1r.z, a1r.w};
            float bw[8] = {b0r.x, b0r.y, b0r.z, b0r.w, b1r.x, b1r.y, b1r.z, b1r.w};
            ushort_t ah[8], al[8], bh[8], bl[8];
#pragma unroll
            for (int j = 0; j < 8; j++) { cvt_hilo(av[j], ah[j], al[j]); cvt_hilo(bw[j], bh[j], bl[j]); }
            *(uint4*)&As_h[nb][arow][apart] = make_uint4(pk(ah[0],ah[1]), pk(ah[2],ah[3]), pk(ah[4],ah[5]), pk(ah[6],ah[7]));
            *(uint4*)&As_l[nb][arow][apart] = make_uint4(pk(al[0],al[1]), pk(al[2],al[3]), pk(al[4],al[5]), pk(al[6],al[7]));
            *(uint4*)&Bs_h[nb][bkr][bj]     = make_uint4(pk(bh[0],bh[1]), pk(bh[2],bh[3]), pk(bh[4],bh[5]), pk(bh[6],bh[7]));
            *(uint4*)&Bs_l[nb][bkr][bj]     = make_uint4(pk(bl[0],bl[1]), pk(bl[2],bl[3]), pk(bl[4],bl[5]), pk(bl[6],bl[7]));
        }
        __syncthreads();
        buf ^= 1;
    }

#pragma unroll
    for (int mi = 0; mi < 4; mi++)
#pragma unroll
        for (int ni = 0; ni < 4; ni++) {
            int gm = m0 + wm * 64 + mi * 16 + (lane >> 2);
            int gc = n0 + wn * 32 + ni * 8 + (lane & 3) * 2;
            float b0f = bo[gc], b1f = bo[gc + 1];
            float* p0 = out + (size_t)gm * Edim + gc;
            *(float2*)p0 = make_float2(C[mi][ni][0] + b0f, C[mi][ni][1] + b1f);
            float* p1 = out + (size_t)(gm + 8) * Edim + gc;
            *(float2*)p1 = make_float2(C[mi][ni][2] + b0f, C[mi][ni][3] + b1f);
        }
}

extern "C" void kernel_launch(void* const* d_in, const int* in_sizes, int n_in,
                              void* d_out, int out_size)
{
    const float* x  = (const float*)d_in[0];
    const float* Wq = (const float*)d_in[1];
    const float* bq = (const float*)d_in[2];
    const float* Wk = (const float*)d_in[3];
    const float* bk = (const float*)d_in[4];
    const float* Wv = (const float*)d_in[5];
    const float* bv = (const float*)d_in[6];
    const float* Wo = (const float*)d_in[7];
    const float* bo = (const float*)d_in[8];
    float* out = (float*)d_out;

    static bool attr_set = false;
    if (!attr_set) {
        cudaFuncSetAttribute(attn_kernel,
            cudaFuncAttributeMaxDynamicSharedMemorySize, ATTN_SMEM_BYTES);
        attr_set = true;
    }

    dim3 g1(Mrows / 128, (3 * Hn * DHd) / 128);   // (32, 24)
    qkv_kernel<<<g1, 256>>>(x, Wq, bq, Wk, bk, Wv, bv);

    dim3 g2(Sdim / 128, Bsz * Hn);                // (16, 32)
    attn_kernel<<<g2, 256, ATTN_SMEM_BYTES>>>();

    dim3 g3(Mrows / 128, Edim / 128);             // (32, 8)
    outproj_kernel<<<g3, 256>>>(Wo, bo, out);
}

// round 11
// speedup vs baseline: 1.3173x; 1.1497x over previous
#include <cuda_runtime.h>
#include <cuda_bf16.h>
#include <cuda_fp16.h>
#include <math.h>

#define Bsz 2
#define Sdim 2048
#define Edim 1024
#define Hn 16
#define DHd 64
#define Adim 1024
#define Mrows (Bsz * Sdim)  // 4096

typedef unsigned short ushort_t;

// Scratch (allocation-free rule: __device__ globals)
__device__ __align__(256) float    g_Q [(size_t)Bsz * Hn * Sdim * DHd];  // [B,H,S,DH]
__device__ __align__(256) ushort_t g_Kh[(size_t)Bsz * Hn * Sdim * DHd];  // K hi bf16
__device__ __align__(256) ushort_t g_Kl[(size_t)Bsz * Hn * Sdim * DHd];  // K lo bf16
__device__ __align__(256) ushort_t g_Vh[(size_t)Bsz * Hn * Sdim * DHd];  // V hi fp16
__device__ __align__(256) ushort_t g_Vl[(size_t)Bsz * Hn * Sdim * DHd];  // V lo fp16
__device__ __align__(256) float    g_O [(size_t)Bsz * Sdim * Adim];      // [B,S,A]
// pre-split weights (bf16 hi/lo)
__device__ __align__(256) ushort_t g_Wqh[(size_t)Hn * Edim * DHd];
__device__ __align__(256) ushort_t g_Wql[(size_t)Hn * Edim * DHd];
__device__ __align__(256) ushort_t g_Wkh[(size_t)Hn * Edim * DHd];
__device__ __align__(256) ushort_t g_Wkl[(size_t)Hn * Edim * DHd];
__device__ __align__(256) ushort_t g_Wvh[(size_t)Hn * Edim * DHd];
__device__ __align__(256) ushort_t g_Wvl[(size_t)Hn * Edim * DHd];
__device__ __align__(256) ushort_t g_Woh[(size_t)Adim * Edim];
__device__ __align__(256) ushort_t g_Wol[(size_t)Adim * Edim];

// ---- mma.sync helpers --------------------------------------------------
__device__ __forceinline__ void ldsm_x4(unsigned* r, const void* p) {
    unsigned addr = (unsigned)__cvta_generic_to_shared(p);
    asm volatile("ldmatrix.sync.aligned.m8n8.x4.shared.b16 {%0,%1,%2,%3}, [%4];"
        : "=r"(r[0]), "=r"(r[1]), "=r"(r[2]), "=r"(r[3]) : "r"(addr));
}
__device__ __forceinline__ void ldsm_x4_t(unsigned* r, const void* p) {
    unsigned addr = (unsigned)__cvta_generic_to_shared(p);
    asm volatile("ldmatrix.sync.aligned.m8n8.x4.trans.shared.b16 {%0,%1,%2,%3}, [%4];"
        : "=r"(r[0]), "=r"(r[1]), "=r"(r[2]), "=r"(r[3]) : "r"(addr));
}
__device__ __forceinline__ void mma_bf16(float* c, const unsigned* a, const unsigned* b) {
    asm volatile("mma.sync.aligned.m16n8k16.row.col.f32.bf16.bf16.f32 "
        "{%0,%1,%2,%3}, {%4,%5,%6,%7}, {%8,%9}, {%0,%1,%2,%3};"
        : "+f"(c[0]), "+f"(c[1]), "+f"(c[2]), "+f"(c[3])
        : "r"(a[0]), "r"(a[1]), "r"(a[2]), "r"(a[3]), "r"(b[0]), "r"(b[1]));
}
__device__ __forceinline__ void mma_f16(float* c, const unsigned* a, const unsigned* b) {
    asm volatile("mma.sync.aligned.m16n8k16.row.col.f32.f16.f16.f32 "
        "{%0,%1,%2,%3}, {%4,%5,%6,%7}, {%8,%9}, {%0,%1,%2,%3};"
        : "+f"(c[0]), "+f"(c[1]), "+f"(c[2]), "+f"(c[3])
        : "r"(a[0]), "r"(a[1]), "r"(a[2]), "r"(a[3]), "r"(b[0]), "r"(b[1]));
}
__device__ __forceinline__ void cvt_hilo(float x, ushort_t& h, ushort_t& l) {
    __nv_bfloat16 bh = __float2bfloat16(x);
    float rem = x - __bfloat162float(bh);
    __nv_bfloat16 bl = __float2bfloat16(rem);
    h = __bfloat16_as_ushort(bh);
    l = __bfloat16_as_ushort(bl);
}
__device__ __forceinline__ unsigned pk(ushort_t a, ushort_t b) {
    return (unsigned)a | ((unsigned)b << 16);
}
__device__ __forceinline__ void hilo_pair(float x, float y, unsigned& h, unsigned& l) {
    ushort_t hx, lx, hy, ly;
    cvt_hilo(x, hx, lx);
    cvt_hilo(y, hy, ly);
    h = pk(hx, hy);
    l = pk(lx, ly);
}
// fp16 hi/lo pair (for V)
__device__ __forceinline__ void hilo_pair_f16(float x, float y, unsigned& h, unsigned& l) {
    __half hx = __float2half_rn(x), hy = __float2half_rn(y);
    float rx = x - __half2float(hx), ry = y - __half2float(hy);
    __half lx = __float2half_rn(rx), ly = __float2half_rn(ry);
    h = (unsigned)__half_as_ushort(hx) | ((unsigned)__half_as_ushort(hy) << 16);
    l = (unsigned)__half_as_ushort(lx) | ((unsigned)__half_as_ushort(ly) << 16);
}
__device__ __forceinline__ unsigned pkf16(float x, float y) {
    __half2 h = __floats2half2_rn(x, y);
    return *(unsigned*)&h;
}
__device__ __forceinline__ float ex2f(float x) {
    float y; asm("ex2.approx.ftz.f32 %0, %1;" : "=f"(y) : "f"(x)); return y;
}
// ---- cp.async ----
__device__ __forceinline__ void cp_async16(void* smem_dst, const void* gmem_src) {
    unsigned d = (unsigned)__cvta_generic_to_shared(smem_dst);
    asm volatile("cp.async.cg.shared.global [%0], [%1], 16;" :: "r"(d), "l"(gmem_src));
}
__device__ __forceinline__ void cp_commit() {
    asm volatile("cp.async.commit_group;" ::: "memory");
}
__device__ __forceinline__ void cp_wait0() {
    asm volatile("cp.async.wait_group 0;" ::: "memory");
}

// ---------------------------------------------------------------------------
// Kernel 0: split fp32 -> bf16 hi/lo (weights only; run once per launch)
// ---------------------------------------------------------------------------
__global__ __launch_bounds__(256) void split_kernel(
    const float* __restrict__ src, ushort_t* __restrict__ dh,
    ushort_t* __restrict__ dl, int n4)
{
    int i = blockIdx.x * blockDim.x + threadIdx.x;
    if (i >= n4) return;
    float4 v = *(const float4*)(src + (size_t)i * 4);
    ushort_t h0, l0, h1, l1, h2, l2, h3, l3;
    cvt_hilo(v.x, h0, l0); cvt_hilo(v.y, h1, l1);
    cvt_hilo(v.z, h2, l2); cvt_hilo(v.w, h3, l3);
    *(uint2*)(dh + (size_t)i * 4) = make_uint2(pk(h0, h1), pk(h2, h3));
    *(uint2*)(dl + (size_t)i * 4) = make_uint2(pk(l0, l1), pk(l2, l3));
}

// ---------------------------------------------------------------------------
// Kernel 1: fused QKV projection. A (x) converted in-kernel (proven),
// B (weights) pure-copy from pre-split arrays. Epilogue: Q fp32,
// K bf16 hi/lo, V fp16 hi/lo.
// ---------------------------------------------------------------------------
__global__ __launch_bounds__(256) void qkv_kernel(
    const float* __restrict__ x,
    const float* __restrict__ bq, const float* __restrict__ bk,
    const float* __restrict__ bv)
{
    __shared__ ushort_t As_h[2][128][24];
    __shared__ ushort_t As_l[2][128][24];
    __shared__ ushort_t Bs_h[2][16][136];
    __shared__ ushort_t Bs_l[2][16][136];

    const int tid = threadIdx.x;
    const int lane = tid & 31;
    const int warp = tid >> 5;
    const int wm = warp & 1;
    const int wn = warp >> 1;
    const int m0 = blockIdx.x * 128;
    const int n0 = blockIdx.y * 128;
    const int z = n0 >> 10;
    const ushort_t* Wh   = (z == 0 ? g_Wqh : (z == 1 ? g_Wkh : g_Wvh));
    const ushort_t* Wl   = (z == 0 ? g_Wql : (z == 1 ? g_Wkl : g_Wvl));
    const float* bias    = (z == 0 ? bq : (z == 1 ? bk : bv));

    const int arow = tid >> 1;
    const int apart = (tid & 1) * 8;
    const float* Ag = x + (size_t)(m0 + arow) * Edim + apart;
    const int bkr = tid >> 4;
    const int bj = (tid & 15) * 8;
    const int cB = n0 + bj;
    const size_t woff = (size_t)((cB >> 6) & 15) * (Edim * DHd) + (cB & 63);
    const ushort_t* Bgh = Wh + woff;
    const ushort_t* Bgl = Wl + woff;

    float C[4][4][4];
#pragma unroll
    for (int i = 0; i < 4; i++)
#pragma unroll
        for (int j = 0; j < 4; j++)
#pragma unroll
            for (int e = 0; e < 4; e++) C[i][j][e] = 0.f;

    float4 a0r, a1r;
    uint4 bH, bL;
    a0r = *(const float4*)(Ag);
    a1r = *(const float4*)(Ag + 4);
    bH = *(const uint4*)(Bgh + (size_t)bkr * DHd);
    bL = *(const uint4*)(Bgl + (size_t)bkr * DHd);
    {
        float av[8] = {a0r.x, a0r.y, a0r.z, a0r.w, a1r.x, a1r.y, a1r.z, a1r.w};
        ushort_t ah[8], al[8];
#pragma unroll
        for (int j = 0; j < 8; j++) cvt_hilo(av[j], ah[j], al[j]);
        *(uint4*)&As_h[0][arow][apart] = make_uint4(pk(ah[0],ah[1]), pk(ah[2],ah[3]), pk(ah[4],ah[5]), pk(ah[6],ah[7]));
        *(uint4*)&As_l[0][arow][apart] = make_uint4(pk(al[0],al[1]), pk(al[2],al[3]), pk(al[4],al[5]), pk(al[6],al[7]));
        *(uint4*)&Bs_h[0][bkr][bj] = bH;
        *(uint4*)&Bs_l[0][bkr][bj] = bL;
    }
    __syncthreads();

    const int lrow = lane & 15;
    const int lkoff = (lane >> 4) * 8;

    int buf = 0;
    for (int k0 = 0; k0 < Edim; k0 += 16) {
        const bool more = (k0 + 16) < Edim;
        if (more) {
            a0r = *(const float4*)(Ag + k0 + 16);
            a1r = *(const float4*)(Ag + k0 + 20);
            bH = *(const uint4*)(Bgh + (size_t)(k0 + 16 + bkr) * DHd);
            bL = *(const uint4*)(Bgl + (size_t)(k0 + 16 + bkr) * DHd);
        }

        unsigned a_hi[4][4], a_lo[4][4], b_hi[4][2], b_lo[4][2];
#pragma unroll
        for (int mi = 0; mi < 4; mi++) {
            ldsm_x4(a_hi[mi], &As_h[buf][wm * 64 + mi * 16 + lrow][lkoff]);
            ldsm_x4(a_lo[mi], &As_l[buf][wm * 64 + mi * 16 + lrow][lkoff]);
        }
#pragma unroll
        for (int np = 0; np < 2; np++) {
            unsigned r[4];
            ldsm_x4_t(r, &Bs_h[buf][lrow][wn * 32 + np * 16 + lkoff]);
            b_hi[2*np][0] = r[0]; b_hi[2*np][1] = r[1];
            b_hi[2*np+1][0] = r[2]; b_hi[2*np+1][1] = r[3];
            ldsm_x4_t(r, &Bs_l[buf][lrow][wn * 32 + np * 16 + lkoff]);
            b_lo[2*np][0] = r[0]; b_lo[2*np][1] = r[1];
            b_lo[2*np+1][0] = r[2]; b_lo[2*np+1][1] = r[3];
        }
#pragma unroll
        for (int mi = 0; mi < 4; mi++)
#pragma unroll
            for (int ni = 0; ni < 4; ni++) {
                mma_bf16(C[mi][ni], a_hi[mi], b_hi[ni]);
                mma_bf16(C[mi][ni], a_hi[mi], b_lo[ni]);
                mma_bf16(C[mi][ni], a_lo[mi], b_hi[ni]);
            }

        if (more) {
            int nb = buf ^ 1;
            float av[8] = {a0r.x, a0r.y, a0r.z, a0r.w, a1r.x, a1r.y, a1r.z, a1r.w};
            ushort_t ah[8], al[8];
#pragma unroll
            for (int j = 0; j < 8; j++) cvt_hilo(av[j], ah[j], al[j]);
            *(uint4*)&As_h[nb][arow][apart] = make_uint4(pk(ah[0],ah[1]), pk(ah[2],ah[3]), pk(ah[4],ah[5]), pk(ah[6],ah[7]));
            *(uint4*)&As_l[nb][arow][apart] = make_uint4(pk(al[0],al[1]), pk(al[2],al[3]), pk(al[4],al[5]), pk(al[6],al[7]));
            *(uint4*)&Bs_h[nb][bkr][bj] = bH;
            *(uint4*)&Bs_l[nb][bkr][bj] = bL;
        }
        __syncthreads();
        buf ^= 1;
    }

    // epilogue: Q fp32; K bf16 hi/lo; V fp16 hi/lo
#pragma unroll
    for (int mi = 0; mi < 4; mi++)
#pragma unroll
        for (int ni = 0; ni < 4; ni++) {
            int gm = m0 + wm * 64 + mi * 16 + (lane >> 2);
            int gc = n0 + wn * 32 + ni * 8 + (lane & 3) * 2;
            float b0f = bias[gc & 1023];
            float b1f = bias[(gc & 1023) + 1];
            int h = (gc >> 6) & 15;
            int d = gc & 63;
            int bb = gm >> 11, s = gm & (Sdim - 1);
            size_t off0 = ((size_t)(bb * Hn + h) * Sdim + s) * DHd + d;
            int gm2 = gm + 8;
            int bb2 = gm2 >> 11, s2 = gm2 & (Sdim - 1);
            size_t off1 = ((size_t)(bb2 * Hn + h) * Sdim + s2) * DHd + d;
            float v00 = C[mi][ni][0] + b0f, v01 = C[mi][ni][1] + b1f;
            float v10 = C[mi][ni][2] + b0f, v11 = C[mi][ni][3] + b1f;
            if (z == 0) {
                *(float2*)(g_Q + off0) = make_float2(v00, v01);
                *(float2*)(g_Q + off1) = make_float2(v10, v11);
            } else if (z == 1) {
                unsigned hh, ll;
                hilo_pair(v00, v01, hh, ll);
                *(unsigned*)(g_Kh + off0) = hh;
                *(unsigned*)(g_Kl + off0) = ll;
                hilo_pair(v10, v11, hh, ll);
                *(unsigned*)(g_Kh + off1) = hh;
                *(unsigned*)(g_Kl + off1) = ll;
            } else {
                unsigned hh, ll;
                hilo_pair_f16(v00, v01, hh, ll);
                *(unsigned*)(g_Vh + off0) = hh;
                *(unsigned*)(g_Vl + off0) = ll;
                hilo_pair_f16(v10, v11, hh, ll);
                *(unsigned*)(g_Vh + off1) = hh;
                *(unsigned*)(g_Vl + off1) = ll;
            }
        }
}

// ---------------------------------------------------------------------------
// Kernel 2: flash attention. QK bf16 hi/lo (3-term); PV fp16 (P single,
// V hi/lo, 2-term). cp.async double-buffered staging (R9-proven structure).
// ---------------------------------------------------------------------------
#define ATILE 4608
#define ABUF  (4 * ATILE)
#define ATTN_SMEM_BYTES (2 * ABUF * 2)

__global__ __launch_bounds__(256) void attn_kernel()
{
    extern __shared__ ushort_t asmem[];

    const int bh = blockIdx.y;
    const int tid = threadIdx.x;
    const int lane = tid & 31;
    const int warp = tid >> 5;

    const float* Qp = g_Q + (size_t)bh * Sdim * DHd;
    const ushort_t* Khp = g_Kh + (size_t)bh * Sdim * DHd;
    const ushort_t* Klp = g_Kl + (size_t)bh * Sdim * DHd;
    const ushort_t* Vhp = g_Vh + (size_t)bh * Sdim * DHd;
    const ushort_t* Vlp = g_Vl + (size_t)bh * Sdim * DHd;

    const float SCALE = 0.125f * 1.4426950408889634f;

    unsigned aq_h[4][4], aq_l[4][4];
    {
        const int r0 = blockIdx.x * 128 + warp * 16 + (lane >> 2);
        const int r1 = r0 + 8;
        const int cb = (lane & 3) * 2;
#pragma unroll
        for (int kk = 0; kk < 4; kk++) {
            float2 v00 = *(const float2*)(Qp + (size_t)r0 * DHd + kk * 16 + cb);
            float2 v01 = *(const float2*)(Qp + (size_t)r0 * DHd + kk * 16 + cb + 8);
            float2 v10 = *(const float2*)(Qp + (size_t)r1 * DHd + kk * 16 + cb);
            float2 v11 = *(const float2*)(Qp + (size_t)r1 * DHd + kk * 16 + cb + 8);
            hilo_pair(v00.x * SCALE, v00.y * SCALE, aq_h[kk][0], aq_l[kk][0]);
            hilo_pair(v10.x * SCALE, v10.y * SCALE, aq_h[kk][1], aq_l[kk][1]);
            hilo_pair(v01.x * SCALE, v01.y * SCALE, aq_h[kk][2], aq_l[kk][2]);
            hilo_pair(v11.x * SCALE, v11.y * SCALE, aq_h[kk][3], aq_l[kk][3]);
        }
    }

    float o[8][4];
#pragma unroll
    for (int i = 0; i < 8; i++)
#pragma unroll
        for (int e = 0; e < 4; e++) o[i][e] = 0.f;
    float m0_ = -INFINITY, m1_ = -INFINITY, l0_ = 0.f, l1_ = 0.f;

    const int l15 = lane & 15;
    const int lk8 = (lane >> 4) * 8;
    const int srow = tid >> 3;
    const int sc8 = (tid & 7) * 8;

#pragma unroll
    for (int i = 0; i < 2; i++) {
        int row = srow + i * 32;
        size_t goff = (size_t)row * DHd + sc8;
        int soff = row * 72 + sc8;
        cp_async16(&asmem[0 * ABUF + 0 * ATILE + soff], Khp + goff);
        cp_async16(&asmem[0 * ABUF + 1 * ATILE + soff], Klp + goff);
        cp_async16(&asmem[0 * ABUF + 2 * ATILE + soff], Vhp + goff);
        cp_async16(&asmem[0 * ABUF + 3 * ATILE + soff], Vlp + goff);
    }
    cp_commit();

    int buf = 0;
    for (int t0 = 0; t0 < Sdim; t0 += 64) {
        cp_wait0();
        __syncthreads();

        const ushort_t* KsH = asmem + buf * ABUF + 0 * ATILE;
        const ushort_t* KsL = asmem + buf * ABUF + 1 * ATILE;
        const ushort_t* VsH = asmem + buf * ABUF + 2 * ATILE;
        const ushort_t* VsL = asmem + buf * ABUF + 3 * ATILE;

        if (t0 + 64 < Sdim) {
            int nb = buf ^ 1;
#pragma unroll
            for (int i = 0; i < 2; i++) {
                int row = srow + i * 32;
                size_t goff = (size_t)(t0 + 64 + row) * DHd + sc8;
                int soff = row * 72 + sc8;
                cp_async16(&asmem[nb * ABUF + 0 * ATILE + soff], Khp + goff);
                cp_async16(&asmem[nb * ABUF + 1 * ATILE + soff], Klp + goff);
                cp_async16(&asmem[nb * ABUF + 2 * ATILE + soff], Vhp + goff);
                cp_async16(&asmem[nb * ABUF + 3 * ATILE + soff], Vlp + goff);
            }
            cp_commit();
        }

        float sc[8][4];
#pragma unroll
        for (int i = 0; i < 8; i++)
#pragma unroll
            for (int e = 0; e < 4; e++) sc[i][e] = 0.f;

#pragma unroll
        for (int kk = 0; kk < 4; kk++) {
#pragma unroll
            for (int pp = 0; pp < 4; pp++) {
                unsigned rh[4], rl[4];
                ldsm_x4(rh, &KsH[(pp * 16 + l15) * 72 + kk * 16 + lk8]);
                ldsm_x4(rl, &KsL[(pp * 16 + l15) * 72 + kk * 16 + lk8]);
                unsigned bh0[2] = {rh[0], rh[2]}, bh1[2] = {rh[1], rh[3]};
                unsigned bl0[2] = {rl[0], rl[2]}, bl1[2] = {rl[1], rl[3]};
                mma_bf16(sc[2*pp],   aq_h[kk], bh0);
                mma_bf16(sc[2*pp],   aq_h[kk], bl0);
                mma_bf16(sc[2*pp],   aq_l[kk], bh0);
                mma_bf16(sc[2*pp+1], aq_h[kk], bh1);
                mma_bf16(sc[2*pp+1], aq_h[kk], bl1);
                mma_bf16(sc[2*pp+1], aq_l[kk], bh1);
            }
        }

        float mx0 = m0_, mx1 = m1_;
#pragma unroll
        for (int i = 0; i < 8; i++) {
            mx0 = fmaxf(mx0, fmaxf(sc[i][0], sc[i][1]));
            mx1 = fmaxf(mx1, fmaxf(sc[i][2], sc[i][3]));
        }
        mx0 = fmaxf(mx0, __shfl_xor_sync(0xffffffffu, mx0, 1));
        mx0 = fmaxf(mx0, __shfl_xor_sync(0xffffffffu, mx0, 2));
        mx1 = fmaxf(mx1, __shfl_xor_sync(0xffffffffu, mx1, 1));
        mx1 = fmaxf(mx1, __shfl_xor_sync(0xffffffffu, mx1, 2));
        if (mx0 > m0_) {
            float corr = ex2f(m0_ - mx0);
            m0_ = mx0; l0_ *= corr;
#pragma unroll
            for (int i = 0; i < 8; i++) { o[i][0] *= corr; o[i][1] *= corr; }
        }
        if (mx1 > m1_) {
            float corr = ex2f(m1_ - mx1);
            m1_ = mx1; l1_ *= corr;
#pragma unroll
            for (int i = 0; i < 8; i++) { o[i][2] *= corr; o[i][3] *= corr; }
        }
        float ts0 = 0.f, ts1 = 0.f;
#pragma unroll
        for (int i = 0; i < 8; i++) {
            sc[i][0] = ex2f(sc[i][0] - m0_);
            sc[i][1] = ex2f(sc[i][1] - m0_);
            sc[i][2] = ex2f(sc[i][2] - m1_);
            sc[i][3] = ex2f(sc[i][3] - m1_);
            ts0 += sc[i][0] + sc[i][1];
            ts1 += sc[i][2] + sc[i][3];
        }
        ts0 += __shfl_xor_sync(0xffffffffu, ts0, 1);
        ts0 += __shfl_xor_sync(0xffffffffu, ts0, 2);
        ts1 += __shfl_xor_sync(0xffffffffu, ts1, 1);
        ts1 += __shfl_xor_sync(0xffffffffu, ts1, 2);
        l0_ += ts0; l1_ += ts1;

        // --- O += P @ V: P fp16 single-term, V fp16 hi/lo (2 MMAs per pair) ---
#pragma unroll
        for (int ss = 0; ss < 4; ss++) {
            unsigned ap[4];
            ap[0] = pkf16(sc[2*ss][0],   sc[2*ss][1]);
            ap[1] = pkf16(sc[2*ss][2],   sc[2*ss][3]);
            ap[2] = pkf16(sc[2*ss+1][0], sc[2*ss+1][1]);
            ap[3] = pkf16(sc[2*ss+1][2], sc[2*ss+1][3]);
#pragma unroll
            for (int np = 0; np < 4; np++) {
                unsigned vh[4], vl[4];
                ldsm_x4_t(vh, &VsH[(ss * 16 + l15) * 72 + np * 16 + lk8]);
                ldsm_x4_t(vl, &VsL[(ss * 16 + l15) * 72 + np * 16 + lk8]);
                unsigned bh0[2] = {vh[0], vh[1]}, bh1[2] = {vh[2], vh[3]};
                unsigned bl0[2] = {vl[0], vl[1]}, bl1[2] = {vl[2], vl[3]};
                mma_f16(o[2*np],   ap, bh0);
                mma_f16(o[2*np],   ap, bl0);
                mma_f16(o[2*np+1], ap, bh1);
                mma_f16(o[2*np+1], ap, bl1);
            }
        }
        __syncthreads();
        buf ^= 1;
    }

    const float inv0 = 1.0f / l0_, inv1 = 1.0f / l1_;
    const int b = bh >> 4, h = bh & 15;
    const int r0 = blockIdx.x * 128 + warp * 16 + (lane >> 2);
    float* op0 = g_O + (size_t)(b * Sdim + r0) * Adim + h * DHd;
    float* op1 = g_O + (size_t)(b * Sdim + r0 + 8) * Adim + h * DHd;
#pragma unroll
    for (int np = 0; np < 8; np++) {
        int col = np * 8 + (lane & 3) * 2;
        *(float2*)(op0 + col) = make_float2(o[np][0] * inv0, o[np][1] * inv0);
        *(float2*)(op1 + col) = make_float2(o[np][2] * inv1, o[np][3] * inv1);
    }
}

// ---------------------------------------------------------------------------
// Kernel 3: output projection. A (g_O) converted in-kernel, B (Wo) pure-copy
// from pre-split arrays.
// ---------------------------------------------------------------------------
__global__ __launch_bounds__(256) void outproj_kernel(
    const float* __restrict__ bo, float* __restrict__ out)
{
    __shared__ ushort_t As_h[2][128][24];
    __shared__ ushort_t As_l[2][128][24];
    __shared__ ushort_t Bs_h[2][16][136];
    __shared__ ushort_t Bs_l[2][16][136];

    const int tid = threadIdx.x;
    const int lane = tid & 31;
    const int warp = tid >> 5;
    const int wm = warp & 1;
    const int wn = warp >> 1;
    const int m0 = blockIdx.x * 128;
    const int n0 = blockIdx.y * 128;

    const int arow = tid >> 1;
    const int apart = (tid & 1) * 8;
    const float* Ag = g_O + (size_t)(m0 + arow) * Adim + apart;
    const int bkr = tid >> 4;
    const int bj = (tid & 15) * 8;
    const ushort_t* Bgh = g_Woh + n0 + bj;
    const ushort_t* Bgl = g_Wol + n0 + bj;

    float C[4][4][4];
#pragma unroll
    for (int i = 0; i < 4; i++)
#pragma unroll
        for (int j = 0; j < 4; j++)
#pragma unroll
            for (int e = 0; e < 4; e++) C[i][j][e] = 0.f;

    float4 a0r, a1r;
    uint4 bH, bL;
    a0r = *(const float4*)(Ag);
    a1r = *(const float4*)(Ag + 4);
    bH = *(const uint4*)(Bgh + (size_t)bkr * Edim);
    bL = *(const uint4*)(Bgl + (size_t)bkr * Edim);
    {
        float av[8] = {a0r.x, a0r.y, a0r.z, a0r.w, a1r.x, a1r.y, a1r.z, a1r.w};
        ushort_t ah[8], al[8];
#pragma unroll
        for (int j = 0; j < 8; j++) cvt_hilo(av[j], ah[j], al[j]);
        *(uint4*)&As_h[0][arow][apart] = make_uint4(pk(ah[0],ah[1]), pk(ah[2],ah[3]), pk(ah[4],ah[5]), pk(ah[6],ah[7]));
        *(uint4*)&As_l[0][arow][apart] = make_uint4(pk(al[0],al[1]), pk(al[2],al[3]), pk(al[4],al[5]), pk(al[6],al[7]));
        *(uint4*)&Bs_h[0][bkr][bj] = bH;
        *(uint4*)&Bs_l[0][bkr][bj] = bL;
    }
    __syncthreads();

    const int lrow = lane & 15;
    const int lkoff = (lane >> 4) * 8;

    int buf = 0;
    for (int k0 = 0; k0 < Adim; k0 += 16) {
        const bool more = (k0 + 16) < Adim;
        if (more) {
            a0r = *(const float4*)(Ag + k0 + 16);
            a1r = *(const float4*)(Ag + k0 + 20);
            bH = *(const uint4*)(Bgh + (size_t)(k0 + 16 + bkr) * Edim);
            bL = *(const uint4*)(Bgl + (size_t)(k0 + 16 + bkr) * Edim);
        }

        unsigned a_hi[4][4], a_lo[4][4], b_hi[4][2], b_lo[4][2];
#pragma unroll
        for (int mi = 0; mi < 4; mi++) {
            ldsm_x4(a_hi[mi], &As_h[buf][wm * 64 + mi * 16 + lrow][lkoff]);
            ldsm_x4(a_lo[mi], &As_l[buf][wm * 64 + mi * 16 + lrow][lkoff]);
        }
#pragma unroll
        for (int np = 0; np < 2; np++) {
            unsigned r[4];
            ldsm_x4_t(r, &Bs_h[buf][lrow][wn * 32 + np * 16 + lkoff]);
            b_hi[2*np][0] = r[0]; b_hi[2*np][1] = r[1];
            b_hi[2*np+1][0] = r[2]; b_hi[2*np+1][1] = r[3];
            ldsm_x4_t(r, &Bs_l[buf][lrow][wn * 32 + np * 16 + lkoff]);
            b_lo[2*np][0] = r[0]; b_lo[2*np][1] = r[1];
            b_lo[2*np+1][0] = r[2]; b_lo[2*np+1][1] = r[3];
        }
#pragma unroll
        for (int mi = 0; mi < 4; mi++)
#pragma unroll
            for (int ni = 0; ni < 4; ni++) {
                mma_bf16(C[mi][ni], a_hi[mi], b_hi[ni]);
                mma_bf16(C[mi][ni], a_hi[mi], b_lo[ni]);
                mma_bf16(C[mi][ni], a_lo[mi], b_hi[ni]);
            }

        if (more) {
            int nb = buf ^ 1;
            float av[8] = {a0r.x, a0r.y, a0r.z, a0r.w, a1r.x, a1r.y, a1r.z, a1r.w};
            ushort_t ah[8], al[8];
#pragma unroll
            for (int j = 0; j < 8; j++) cvt_hilo(av[j], ah[j], al[j]);
            *(uint4*)&As_h[nb][arow][apart] = make_uint4(pk(ah[0],ah[1]), pk(ah[2],ah[3]), pk(ah[4],ah[5]), pk(ah[6],ah[7]));
            *(uint4*)&As_l[nb][arow][apart] = make_uint4(pk(al[0],al[1]), pk(al[2],al[3]), pk(al[4],al[5]), pk(al[6],al[7]));
            *(uint4*)&Bs_h[nb][bkr][bj] = bH;
            *(uint4*)&Bs_l[nb][bkr][bj] = bL;
        }
        __syncthreads();
        buf ^= 1;
    }

#pragma unroll
    for (int mi = 0; mi < 4; mi++)
#pragma unroll
        for (int ni = 0; ni < 4; ni++) {
            int gm = m0 + wm * 64 + mi * 16 + (lane >> 2);
            int gc = n0 + wn * 32 + ni * 8 + (lane & 3) * 2;
            float b0f = bo[gc], b1f = bo[gc + 1];
            float* p0 = out + (size_t)gm * Edim + gc;
            *(float2*)p0 = make_float2(C[mi][ni][0] + b0f, C[mi][ni][1] + b1f);
            float* p1 = out + (size_t)(gm + 8) * Edim + gc;
            *(float2*)p1 = make_float2(C[mi][ni][2] + b0f, C[mi][ni][3] + b1f);
        }
}

extern "C" void kernel_launch(void* const* d_in, const int* in_sizes, int n_in,
                              void* d_out, int out_size)
{
    const float* x  = (const float*)d_in[0];
    const float* Wq = (const float*)d_in[1];
    const float* bq = (const float*)d_in[2];
    const float* Wk = (const float*)d_in[3];
    const float* bk = (const float*)d_in[4];
    const float* Wv = (const float*)d_in[5];
    const float* bv = (const float*)d_in[6];
    const float* Wo = (const float*)d_in[7];
    const float* bo = (const float*)d_in[8];
    float* out = (float*)d_out;

    static bool attr_set = false;
    if (!attr_set) {
        cudaFuncSetAttribute(attn_kernel,
            cudaFuncAttributeMaxDynamicSharedMemorySize, ATTN_SMEM_BYTES);
        attr_set = true;
    }

    ushort_t *wqh, *wql, *wkh, *wkl, *wvh, *wvl, *woh, *wol;
    cudaGetSymbolAddress((void**)&wqh, g_Wqh); cudaGetSymbolAddress((void**)&wql, g_Wql);
    cudaGetSymbolAddress((void**)&wkh, g_Wkh); cudaGetSymbolAddress((void**)&wkl, g_Wkl);
    cudaGetSymbolAddress((void**)&wvh, g_Wvh); cudaGetSymbolAddress((void**)&wvl, g_Wvl);
    cudaGetSymbolAddress((void**)&woh, g_Woh); cudaGetSymbolAddress((void**)&wol, g_Wol);

    const int nW = Hn * Edim * DHd / 4;       // 262,144 float4s
    split_kernel<<<(nW + 255) / 256, 256>>>(Wq, wqh, wql, nW);
    split_kernel<<<(nW + 255) / 256, 256>>>(Wk, wkh, wkl, nW);
    split_kernel<<<(nW + 255) / 256, 256>>>(Wv, wvh, wvl, nW);
    split_kernel<<<(nW + 255) / 256, 256>>>(Wo, woh, wol, nW);

    dim3 g1(Mrows / 128, (3 * Hn * DHd) / 128);   // (32, 24)
    qkv_kernel<<<g1, 256>>>(x, bq, bk, bv);

    dim3 g2(Sdim / 128, Bsz * Hn);                // (16, 32)
    attn_kernel<<<g2, 256, ATTN_SMEM_BYTES>>>();

    dim3 g3(Mrows / 128, Edim / 128);             // (32, 8)
    outproj_kernel<<<g3, 256>>>(bo, out);
}

// round 12
// speedup vs baseline: 1.7165x; 1.3031x over previous
#include <cuda_runtime.h>
#include <cuda_bf16.h>
#include <cuda_fp16.h>
#include <math.h>

#define Bsz 2
#define Sdim 2048
#define Edim 1024
#define Hn 16
#define DHd 64
#define Adim 1024
#define Mrows (Bsz * Sdim)  // 4096

typedef unsigned short ushort_t;

// Scratch (allocation-free rule: __device__ globals)
__device__ __align__(256) float    g_Q [(size_t)Bsz * Hn * Sdim * DHd];  // [B,H,S,DH]
__device__ __align__(256) ushort_t g_Kf[(size_t)Bsz * Hn * Sdim * DHd];  // K fp16
__device__ __align__(256) ushort_t g_Vf[(size_t)Bsz * Hn * Sdim * DHd];  // V fp16
__device__ __align__(256) float    g_O [(size_t)Bsz * Sdim * Adim];      // [B,S,A]
// pre-split weights (bf16 hi/lo)
__device__ __align__(256) ushort_t g_Wqh[(size_t)Hn * Edim * DHd];
__device__ __align__(256) ushort_t g_Wql[(size_t)Hn * Edim * DHd];
__device__ __align__(256) ushort_t g_Wkh[(size_t)Hn * Edim * DHd];
__device__ __align__(256) ushort_t g_Wkl[(size_t)Hn * Edim * DHd];
__device__ __align__(256) ushort_t g_Wvh[(size_t)Hn * Edim * DHd];
__device__ __align__(256) ushort_t g_Wvl[(size_t)Hn * Edim * DHd];
__device__ __align__(256) ushort_t g_Woh[(size_t)Adim * Edim];
__device__ __align__(256) ushort_t g_Wol[(size_t)Adim * Edim];

// ---- mma.sync helpers --------------------------------------------------
__device__ __forceinline__ void ldsm_x4(unsigned* r, const void* p) {
    unsigned addr = (unsigned)__cvta_generic_to_shared(p);
    asm volatile("ldmatrix.sync.aligned.m8n8.x4.shared.b16 {%0,%1,%2,%3}, [%4];"
        : "=r"(r[0]), "=r"(r[1]), "=r"(r[2]), "=r"(r[3]) : "r"(addr));
}
__device__ __forceinline__ void ldsm_x4_t(unsigned* r, const void* p) {
    unsigned addr = (unsigned)__cvta_generic_to_shared(p);
    asm volatile("ldmatrix.sync.aligned.m8n8.x4.trans.shared.b16 {%0,%1,%2,%3}, [%4];"
        : "=r"(r[0]), "=r"(r[1]), "=r"(r[2]), "=r"(r[3]) : "r"(addr));
}
__device__ __forceinline__ void mma_bf16(float* c, const unsigned* a, const unsigned* b) {
    asm volatile("mma.sync.aligned.m16n8k16.row.col.f32.bf16.bf16.f32 "
        "{%0,%1,%2,%3}, {%4,%5,%6,%7}, {%8,%9}, {%0,%1,%2,%3};"
        : "+f"(c[0]), "+f"(c[1]), "+f"(c[2]), "+f"(c[3])
        : "r"(a[0]), "r"(a[1]), "r"(a[2]), "r"(a[3]), "r"(b[0]), "r"(b[1]));
}
__device__ __forceinline__ void mma_f16(float* c, const unsigned* a, const unsigned* b) {
    asm volatile("mma.sync.aligned.m16n8k16.row.col.f32.f16.f16.f32 "
        "{%0,%1,%2,%3}, {%4,%5,%6,%7}, {%8,%9}, {%0,%1,%2,%3};"
        : "+f"(c[0]), "+f"(c[1]), "+f"(c[2]), "+f"(c[3])
        : "r"(a[0]), "r"(a[1]), "r"(a[2]), "r"(a[3]), "r"(b[0]), "r"(b[1]));
}
__device__ __forceinline__ void cvt_hilo(float x, ushort_t& h, ushort_t& l) {
    __nv_bfloat16 bh = __float2bfloat16(x);
    float rem = x - __bfloat162float(bh);
    __nv_bfloat16 bl = __float2bfloat16(rem);
    h = __bfloat16_as_ushort(bh);
    l = __bfloat16_as_ushort(bl);
}
__device__ __forceinline__ unsigned pk(ushort_t a, ushort_t b) {
    return (unsigned)a | ((unsigned)b << 16);
}
__device__ __forceinline__ void hilo_pair(float x, float y, unsigned& h, unsigned& l) {
    ushort_t hx, lx, hy, ly;
    cvt_hilo(x, hx, lx);
    cvt_hilo(y, hy, ly);
    h = pk(hx, hy);
    l = pk(lx, ly);
}
// fp16 hi/lo pair (for Q registers)
__device__ __forceinline__ void hilo_pair_f16(float x, float y, unsigned& h, unsigned& l) {
    __half hx = __float2half_rn(x), hy = __float2half_rn(y);
    float rx = x - __half2float(hx), ry = y - __half2float(hy);
    __half lx = __float2half_rn(rx), ly = __float2half_rn(ry);
    h = (unsigned)__half_as_ushort(hx) | ((unsigned)__half_as_ushort(hy) << 16);
    l = (unsigned)__half_as_ushort(lx) | ((unsigned)__half_as_ushort(ly) << 16);
}
__device__ __forceinline__ unsigned pkf16(float x, float y) {
    __half2 h = __floats2half2_rn(x, y);
    return *(unsigned*)&h;
}
__device__ __forceinline__ float ex2f(float x) {
    float y; asm("ex2.approx.ftz.f32 %0, %1;" : "=f"(y) : "f"(x)); return y;
}
// ---- cp.async ----
__device__ __forceinline__ void cp_async16(void* smem_dst, const void* gmem_src) {
    unsigned d = (unsigned)__cvta_generic_to_shared(smem_dst);
    asm volatile("cp.async.cg.shared.global [%0], [%1], 16;" :: "r"(d), "l"(gmem_src));
}
__device__ __forceinline__ void cp_commit() {
    asm volatile("cp.async.commit_group;" ::: "memory");
}
__device__ __forceinline__ void cp_wait0() {
    asm volatile("cp.async.wait_group 0;" ::: "memory");
}

// ---------------------------------------------------------------------------
// Kernel 0: split all 4 weight matrices fp32 -> bf16 hi/lo in ONE launch.
// grid = (n4/256, 4); blockIdx.y selects the weight.
// ---------------------------------------------------------------------------
__global__ __launch_bounds__(256) void split4_kernel(
    const float* __restrict__ s0, const float* __restrict__ s1,
    const float* __restrict__ s2, const float* __restrict__ s3, int n4)
{
    int i = blockIdx.x * blockDim.x + threadIdx.x;
    if (i >= n4) return;
    const float* src;
    ushort_t *dh, *dl;
    switch (blockIdx.y) {
        case 0: src = s0; dh = g_Wqh; dl = g_Wql; break;
        case 1: src = s1; dh = g_Wkh; dl = g_Wkl; break;
        case 2: src = s2; dh = g_Wvh; dl = g_Wvl; break;
        default: src = s3; dh = g_Woh; dl = g_Wol; break;
    }
    float4 v = *(const float4*)(src + (size_t)i * 4);
    ushort_t h0, l0, h1, l1, h2, l2, h3, l3;
    cvt_hilo(v.x, h0, l0); cvt_hilo(v.y, h1, l1);
    cvt_hilo(v.z, h2, l2); cvt_hilo(v.w, h3, l3);
    *(uint2*)(dh + (size_t)i * 4) = make_uint2(pk(h0, h1), pk(h2, h3));
    *(uint2*)(dl + (size_t)i * 4) = make_uint2(pk(l0, l1), pk(l2, l3));
}

// ---------------------------------------------------------------------------
// Kernel 1: fused QKV projection. A (x) converted in-kernel, B pure-copy
// from pre-split weights. Epilogue: Q fp32, K fp16, V fp16.
// ---------------------------------------------------------------------------
__global__ __launch_bounds__(256) void qkv_kernel(
    const float* __restrict__ x,
    const float* __restrict__ bq, const float* __restrict__ bk,
    const float* __restrict__ bv)
{
    __shared__ ushort_t As_h[2][128][24];
    __shared__ ushort_t As_l[2][128][24];
    __shared__ ushort_t Bs_h[2][16][136];
    __shared__ ushort_t Bs_l[2][16][136];

    const int tid = threadIdx.x;
    const int lane = tid & 31;
    const int warp = tid >> 5;
    const int wm = warp & 1;
    const int wn = warp >> 1;
    const int m0 = blockIdx.x * 128;
    const int n0 = blockIdx.y * 128;
    const int z = n0 >> 10;
    const ushort_t* Wh   = (z == 0 ? g_Wqh : (z == 1 ? g_Wkh : g_Wvh));
    const ushort_t* Wl   = (z == 0 ? g_Wql : (z == 1 ? g_Wkl : g_Wvl));
    const float* bias    = (z == 0 ? bq : (z == 1 ? bk : bv));

    const int arow = tid >> 1;
    const int apart = (tid & 1) * 8;
    const float* Ag = x + (size_t)(m0 + arow) * Edim + apart;
    const int bkr = tid >> 4;
    const int bj = (tid & 15) * 8;
    const int cB = n0 + bj;
    const size_t woff = (size_t)((cB >> 6) & 15) * (Edim * DHd) + (cB & 63);
    const ushort_t* Bgh = Wh + woff;
    const ushort_t* Bgl = Wl + woff;

    float C[4][4][4];
#pragma unroll
    for (int i = 0; i < 4; i++)
#pragma unroll
        for (int j = 0; j < 4; j++)
#pragma unroll
            for (int e = 0; e < 4; e++) C[i][j][e] = 0.f;

    float4 a0r, a1r;
    uint4 bH, bL;
    a0r = *(const float4*)(Ag);
    a1r = *(const float4*)(Ag + 4);
    bH = *(const uint4*)(Bgh + (size_t)bkr * DHd);
    bL = *(const uint4*)(Bgl + (size_t)bkr * DHd);
    {
        float av[8] = {a0r.x, a0r.y, a0r.z, a0r.w, a1r.x, a1r.y, a1r.z, a1r.w};
        ushort_t ah[8], al[8];
#pragma unroll
        for (int j = 0; j < 8; j++) cvt_hilo(av[j], ah[j], al[j]);
        *(uint4*)&As_h[0][arow][apart] = make_uint4(pk(ah[0],ah[1]), pk(ah[2],ah[3]), pk(ah[4],ah[5]), pk(ah[6],ah[7]));
        *(uint4*)&As_l[0][arow][apart] = make_uint4(pk(al[0],al[1]), pk(al[2],al[3]), pk(al[4],al[5]), pk(al[6],al[7]));
        *(uint4*)&Bs_h[0][bkr][bj] = bH;
        *(uint4*)&Bs_l[0][bkr][bj] = bL;
    }
    __syncthreads();

    const int lrow = lane & 15;
    const int lkoff = (lane >> 4) * 8;

    int buf = 0;
    for (int k0 = 0; k0 < Edim; k0 += 16) {
        const bool more = (k0 + 16) < Edim;
        if (more) {
            a0r = *(const float4*)(Ag + k0 + 16);
            a1r = *(const float4*)(Ag + k0 + 20);
            bH = *(const uint4*)(Bgh + (size_t)(k0 + 16 + bkr) * DHd);
            bL = *(const uint4*)(Bgl + (size_t)(k0 + 16 + bkr) * DHd);
        }

        unsigned a_hi[4][4], a_lo[4][4], b_hi[4][2], b_lo[4][2];
#pragma unroll
        for (int mi = 0; mi < 4; mi++) {
            ldsm_x4(a_hi[mi], &As_h[buf][wm * 64 + mi * 16 + lrow][lkoff]);
            ldsm_x4(a_lo[mi], &As_l[buf][wm * 64 + mi * 16 + lrow][lkoff]);
        }
#pragma unroll
        for (int np = 0; np < 2; np++) {
            unsigned r[4];
            ldsm_x4_t(r, &Bs_h[buf][lrow][wn * 32 + np * 16 + lkoff]);
            b_hi[2*np][0] = r[0]; b_hi[2*np][1] = r[1];
            b_hi[2*np+1][0] = r[2]; b_hi[2*np+1][1] = r[3];
            ldsm_x4_t(r, &Bs_l[buf][lrow][wn * 32 + np * 16 + lkoff]);
            b_lo[2*np][0] = r[0]; b_lo[2*np][1] = r[1];
            b_lo[2*np+1][0] = r[2]; b_lo[2*np+1][1] = r[3];
        }
#pragma unroll
        for (int mi = 0; mi < 4; mi++)
#pragma unroll
            for (int ni = 0; ni < 4; ni++) {
                mma_bf16(C[mi][ni], a_hi[mi], b_hi[ni]);
                mma_bf16(C[mi][ni], a_hi[mi], b_lo[ni]);
                mma_bf16(C[mi][ni], a_lo[mi], b_hi[ni]);
            }

        if (more) {
            int nb = buf ^ 1;
            float av[8] = {a0r.x, a0r.y, a0r.z, a0r.w, a1r.x, a1r.y, a1r.z, a1r.w};
            ushort_t ah[8], al[8];
#pragma unroll
            for (int j = 0; j < 8; j++) cvt_hilo(av[j], ah[j], al[j]);
            *(uint4*)&As_h[nb][arow][apart] = make_uint4(pk(ah[0],ah[1]), pk(ah[2],ah[3]), pk(ah[4],ah[5]), pk(ah[6],ah[7]));
            *(uint4*)&As_l[nb][arow][apart] = make_uint4(pk(al[0],al[1]), pk(al[2],al[3]), pk(al[4],al[5]), pk(al[6],al[7]));
            *(uint4*)&Bs_h[nb][bkr][bj] = bH;
            *(uint4*)&Bs_l[nb][bkr][bj] = bL;
        }
        __syncthreads();
        buf ^= 1;
    }

    // epilogue: Q fp32; K fp16; V fp16
#pragma unroll
    for (int mi = 0; mi < 4; mi++)
#pragma unroll
        for (int ni = 0; ni < 4; ni++) {
            int gm = m0 + wm * 64 + mi * 16 + (lane >> 2);
            int gc = n0 + wn * 32 + ni * 8 + (lane & 3) * 2;
            float b0f = bias[gc & 1023];
            float b1f = bias[(gc & 1023) + 1];
            int h = (gc >> 6) & 15;
            int d = gc & 63;
            int bb = gm >> 11, s = gm & (Sdim - 1);
            size_t off0 = ((size_t)(bb * Hn + h) * Sdim + s) * DHd + d;
            int gm2 = gm + 8;
            int bb2 = gm2 >> 11, s2 = gm2 & (Sdim - 1);
            size_t off1 = ((size_t)(bb2 * Hn + h) * Sdim + s2) * DHd + d;
            float v00 = C[mi][ni][0] + b0f, v01 = C[mi][ni][1] + b1f;
            float v10 = C[mi][ni][2] + b0f, v11 = C[mi][ni][3] + b1f;
            if (z == 0) {
                *(float2*)(g_Q + off0) = make_float2(v00, v01);
                *(float2*)(g_Q + off1) = make_float2(v10, v11);
            } else {
                ushort_t* dst = (z == 1 ? g_Kf : g_Vf);
                *(unsigned*)(dst + off0) = pkf16(v00, v01);
                *(unsigned*)(dst + off1) = pkf16(v10, v11);
            }
        }
}

// ---------------------------------------------------------------------------
// Kernel 2: flash attention, fp16. QK: Q hi/lo fp16 x K fp16 (2-term);
// PV: P fp16 x V fp16 (1-term). cp.async double-buffered 2-array staging.
// ---------------------------------------------------------------------------
#define ATILE 4608            // 64*72 ushorts per array
#define ABUF  (2 * ATILE)
#define ATTN_SMEM_BYTES (2 * ABUF * 2)   // 36,864 B

__global__ __launch_bounds__(256) void attn_kernel()
{
    extern __shared__ ushort_t asmem[];

    const int bh = blockIdx.y;
    const int tid = threadIdx.x;
    const int lane = tid & 31;
    const int warp = tid >> 5;

    const float* Qp = g_Q + (size_t)bh * Sdim * DHd;
    const ushort_t* Kp = g_Kf + (size_t)bh * Sdim * DHd;
    const ushort_t* Vp = g_Vf + (size_t)bh * Sdim * DHd;

    const float SCALE = 0.125f * 1.4426950408889634f;

    unsigned aq_h[4][4], aq_l[4][4];
    {
        const int r0 = blockIdx.x * 128 + warp * 16 + (lane >> 2);
        const int r1 = r0 + 8;
        const int cb = (lane & 3) * 2;
#pragma unroll
        for (int kk = 0; kk < 4; kk++) {
            float2 v00 = *(const float2*)(Qp + (size_t)r0 * DHd + kk * 16 + cb);
            float2 v01 = *(const float2*)(Qp + (size_t)r0 * DHd + kk * 16 + cb + 8);
            float2 v10 = *(const float2*)(Qp + (size_t)r1 * DHd + kk * 16 + cb);
            float2 v11 = *(const float2*)(Qp + (size_t)r1 * DHd + kk * 16 + cb + 8);
            hilo_pair_f16(v00.x * SCALE, v00.y * SCALE, aq_h[kk][0], aq_l[kk][0]);
            hilo_pair_f16(v10.x * SCALE, v10.y * SCALE, aq_h[kk][1], aq_l[kk][1]);
            hilo_pair_f16(v01.x * SCALE, v01.y * SCALE, aq_h[kk][2], aq_l[kk][2]);
            hilo_pair_f16(v11.x * SCALE, v11.y * SCALE, aq_h[kk][3], aq_l[kk][3]);
        }
    }

    float o[8][4];
#pragma unroll
    for (int i = 0; i < 8; i++)
#pragma unroll
        for (int e = 0; e < 4; e++) o[i][e] = 0.f;
    float m0_ = -INFINITY, m1_ = -INFINITY, l0_ = 0.f, l1_ = 0.f;

    const int l15 = lane & 15;
    const int lk8 = (lane >> 4) * 8;
    const int srow = tid >> 3;
    const int sc8 = (tid & 7) * 8;

#pragma unroll
    for (int i = 0; i < 2; i++) {
        int row = srow + i * 32;
        size_t goff = (size_t)row * DHd + sc8;
        int soff = row * 72 + sc8;
        cp_async16(&asmem[0 * ABUF + 0 * ATILE + soff], Kp + goff);
        cp_async16(&asmem[0 * ABUF + 1 * ATILE + soff], Vp + goff);
    }
    cp_commit();

    int buf = 0;
    for (int t0 = 0; t0 < Sdim; t0 += 64) {
        cp_wait0();
        __syncthreads();

        const ushort_t* Ks = asmem + buf * ABUF + 0 * ATILE;
        const ushort_t* Vs = asmem + buf * ABUF + 1 * ATILE;

        if (t0 + 64 < Sdim) {
            int nb = buf ^ 1;
#pragma unroll
            for (int i = 0; i < 2; i++) {
                int row = srow + i * 32;
                size_t goff = (size_t)(t0 + 64 + row) * DHd + sc8;
                int soff = row * 72 + sc8;
                cp_async16(&asmem[nb * ABUF + 0 * ATILE + soff], Kp + goff);
                cp_async16(&asmem[nb * ABUF + 1 * ATILE + soff], Vp + goff);
            }
            cp_commit();
        }

        float sc[8][4];
#pragma unroll
        for (int i = 0; i < 8; i++)
#pragma unroll
            for (int e = 0; e < 4; e++) sc[i][e] = 0.f;

#pragma unroll
        for (int kk = 0; kk < 4; kk++) {
#pragma unroll
            for (int pp = 0; pp < 4; pp++) {
                unsigned rk[4];
                ldsm_x4(rk, &Ks[(pp * 16 + l15) * 72 + kk * 16 + lk8]);
                unsigned bk0[2] = {rk[0], rk[2]}, bk1[2] = {rk[1], rk[3]};
                mma_f16(sc[2*pp],   aq_h[kk], bk0);
                mma_f16(sc[2*pp],   aq_l[kk], bk0);
                mma_f16(sc[2*pp+1], aq_h[kk], bk1);
                mma_f16(sc[2*pp+1], aq_l[kk], bk1);
            }
        }

        float mx0 = m0_, mx1 = m1_;
#pragma unroll
        for (int i = 0; i < 8; i++) {
            mx0 = fmaxf(mx0, fmaxf(sc[i][0], sc[i][1]));
            mx1 = fmaxf(mx1, fmaxf(sc[i][2], sc[i][3]));
        }
        mx0 = fmaxf(mx0, __shfl_xor_sync(0xffffffffu, mx0, 1));
        mx0 = fmaxf(mx0, __shfl_xor_sync(0xffffffffu, mx0, 2));
        mx1 = fmaxf(mx1, __shfl_xor_sync(0xffffffffu, mx1, 1));
        mx1 = fmaxf(mx1, __shfl_xor_sync(0xffffffffu, mx1, 2));
        if (mx0 > m0_) {
            float corr = ex2f(m0_ - mx0);
            m0_ = mx0; l0_ *= corr;
#pragma unroll
            for (int i = 0; i < 8; i++) { o[i][0] *= corr; o[i][1] *= corr; }
        }
        if (mx1 > m1_) {
            float corr = ex2f(m1_ - mx1);
            m1_ = mx1; l1_ *= corr;
#pragma unroll
            for (int i = 0; i < 8; i++) { o[i][2] *= corr; o[i][3] *= corr; }
        }
        float ts0 = 0.f, ts1 = 0.f;
#pragma unroll
        for (int i = 0; i < 8; i++) {
            sc[i][0] = ex2f(sc[i][0] - m0_);
            sc[i][1] = ex2f(sc[i][1] - m0_);
            sc[i][2] = ex2f(sc[i][2] - m1_);
            sc[i][3] = ex2f(sc[i][3] - m1_);
            ts0 += sc[i][0] + sc[i][1];
            ts1 += sc[i][2] + sc[i][3];
        }
        ts0 += __shfl_xor_sync(0xffffffffu, ts0, 1);
        ts0 += __shfl_xor_sync(0xffffffffu, ts0, 2);
        ts1 += __shfl_xor_sync(0xffffffffu, ts1, 1);
        ts1 += __shfl_xor_sync(0xffffffffu, ts1, 2);
        l0_ += ts0; l1_ += ts1;

        // --- O += P @ V: both single fp16 ---
#pragma unroll
        for (int ss = 0; ss < 4; ss++) {
            unsigned ap[4];
            ap[0] = pkf16(sc[2*ss][0],   sc[2*ss][1]);
            ap[1] = pkf16(sc[2*ss][2],   sc[2*ss][3]);
            ap[2] = pkf16(sc[2*ss+1][0], sc[2*ss+1][1]);
            ap[3] = pkf16(sc[2*ss+1][2], sc[2*ss+1][3]);
#pragma unroll
            for (int np = 0; np < 4; np++) {
                unsigned vv[4];
                ldsm_x4_t(vv, &Vs[(ss * 16 + l15) * 72 + np * 16 + lk8]);
                unsigned b0[2] = {vv[0], vv[1]}, b1[2] = {vv[2], vv[3]};
                mma_f16(o[2*np],   ap, b0);
                mma_f16(o[2*np+1], ap, b1);
            }
        }
        __syncthreads();
        buf ^= 1;
    }

    const float inv0 = 1.0f / l0_, inv1 = 1.0f / l1_;
    const int b = bh >> 4, h = bh & 15;
    const int r0 = blockIdx.x * 128 + warp * 16 + (lane >> 2);
    float* op0 = g_O + (size_t)(b * Sdim + r0) * Adim + h * DHd;
    float* op1 = g_O + (size_t)(b * Sdim + r0 + 8) * Adim + h * DHd;
#pragma unroll
    for (int np = 0; np < 8; np++) {
        int col = np * 8 + (lane & 3) * 2;
        *(float2*)(op0 + col) = make_float2(o[np][0] * inv0, o[np][1] * inv0);
        *(float2*)(op1 + col) = make_float2(o[np][2] * inv1, o[np][3] * inv1);
    }
}

// ---------------------------------------------------------------------------
// Kernel 3: output projection. A (g_O) converted in-kernel, B (Wo) pure-copy.
// ---------------------------------------------------------------------------
__global__ __launch_bounds__(256) void outproj_kernel(
    const float* __restrict__ bo, float* __restrict__ out)
{
    __shared__ ushort_t As_h[2][128][24];
    __shared__ ushort_t As_l[2][128][24];
    __shared__ ushort_t Bs_h[2][16][136];
    __shared__ ushort_t Bs_l[2][16][136];

    const int tid = threadIdx.x;
    const int lane = tid & 31;
    const int warp = tid >> 5;
    const int wm = warp & 1;
    const int wn = warp >> 1;
    const int m0 = blockIdx.x * 128;
    const int n0 = blockIdx.y * 128;

    const int arow = tid >> 1;
    const int apart = (tid & 1) * 8;
    const float* Ag = g_O + (size_t)(m0 + arow) * Adim + apart;
    const int bkr = tid >> 4;
    const int bj = (tid & 15) * 8;
    const ushort_t* Bgh = g_Woh + n0 + bj;
    const ushort_t* Bgl = g_Wol + n0 + bj;

    float C[4][4][4];
#pragma unroll
    for (int i = 0; i < 4; i++)
#pragma unroll
        for (int j = 0; j < 4; j++)
#pragma unroll
            for (int e = 0; e < 4; e++) C[i][j][e] = 0.f;

    float4 a0r, a1r;
    uint4 bH, bL;
    a0r = *(const float4*)(Ag);
    a1r = *(const float4*)(Ag + 4);
    bH = *(const uint4*)(Bgh + (size_t)bkr * Edim);
    bL = *(const uint4*)(Bgl + (size_t)bkr * Edim);
    {
        float av[8] = {a0r.x, a0r.y, a0r.z, a0r.w, a1r.x, a1r.y, a1r.z, a1r.w};
        ushort_t ah[8], al[8];
#pragma unroll
        for (int j = 0; j < 8; j++) cvt_hilo(av[j], ah[j], al[j]);
        *(uint4*)&As_h[0][arow][apart] = make_uint4(pk(ah[0],ah[1]), pk(ah[2],ah[3]), pk(ah[4],ah[5]), pk(ah[6],ah[7]));
        *(uint4*)&As_l[0][arow][apart] = make_uint4(pk(al[0],al[1]), pk(al[2],al[3]), pk(al[4],al[5]), pk(al[6],al[7]));
        *(uint4*)&Bs_h[0][bkr][bj] = bH;
        *(uint4*)&Bs_l[0][bkr][bj] = bL;
    }
    __syncthreads();

    const int lrow = lane & 15;
    const int lkoff = (lane >> 4) * 8;

    int buf = 0;
    for (int k0 = 0; k0 < Adim; k0 += 16) {
        const bool more = (k0 + 16) < Adim;
        if (more) {
            a0r = *(const float4*)(Ag + k0 + 16);
            a1r = *(const float4*)(Ag + k0 + 20);
            bH = *(const uint4*)(Bgh + (size_t)(k0 + 16 + bkr) * Edim);
            bL = *(const uint4*)(Bgl + (size_t)(k0 + 16 + bkr) * Edim);
        }

        unsigned a_hi[4][4], a_lo[4][4], b_hi[4][2], b_lo[4][2];
#pragma unroll
        for (int mi = 0; mi < 4; mi++) {
            ldsm_x4(a_hi[mi], &As_h[buf][wm * 64 + mi * 16 + lrow][lkoff]);
            ldsm_x4(a_lo[mi], &As_l[buf][wm * 64 + mi * 16 + lrow][lkoff]);
        }
#pragma unroll
        for (int np = 0; np < 2; np++) {
            unsigned r[4];
            ldsm_x4_t(r, &Bs_h[buf][lrow][wn * 32 + np * 16 + lkoff]);
            b_hi[2*np][0] = r[0]; b_hi[2*np][1] = r[1];
            b_hi[2*np+1][0] = r[2]; b_hi[2*np+1][1] = r[3];
            ldsm_x4_t(r, &Bs_l[buf][lrow][wn * 32 + np * 16 + lkoff]);
            b_lo[2*np][0] = r[0]; b_lo[2*np][1] = r[1];
            b_lo[2*np+1][0] = r[2]; b_lo[2*np+1][1] = r[3];
        }
#pragma unroll
        for (int mi = 0; mi < 4; mi++)
#pragma unroll
            for (int ni = 0; ni < 4; ni++) {
                mma_bf16(C[mi][ni], a_hi[mi], b_hi[ni]);
                mma_bf16(C[mi][ni], a_hi[mi], b_lo[ni]);
                mma_bf16(C[mi][ni], a_lo[mi], b_hi[ni]);
            }

        if (more) {
            int nb = buf ^ 1;
            float av[8] = {a0r.x, a0r.y, a0r.z, a0r.w, a1r.x, a1r.y, a1r.z, a1r.w};
            ushort_t ah[8], al[8];
#pragma unroll
            for (int j = 0; j < 8; j++) cvt_hilo(av[j], ah[j], al[j]);
            *(uint4*)&As_h[nb][arow][apart] = make_uint4(pk(ah[0],ah[1]), pk(ah[2],ah[3]), pk(ah[4],ah[5]), pk(ah[6],ah[7]));
            *(uint4*)&As_l[nb][arow][apart] = make_uint4(pk(al[0],al[1]), pk(al[2],al[3]), pk(al[4],al[5]), pk(al[6],al[7]));
            *(uint4*)&Bs_h[nb][bkr][bj] = bH;
            *(uint4*)&Bs_l[nb][bkr][bj] = bL;
        }
        __syncthreads();
        buf ^= 1;
    }

#pragma unroll
    for (int mi = 0; mi < 4; mi++)
#pragma unroll
        for (int ni = 0; ni < 4; ni++) {
            int gm = m0 + wm * 64 + mi * 16 + (lane >> 2);
            int gc = n0 + wn * 32 + ni * 8 + (lane & 3) * 2;
            float b0f = bo[gc], b1f = bo[gc + 1];
            float* p0 = out + (size_t)gm * Edim + gc;
            *(float2*)p0 = make_float2(C[mi][ni][0] + b0f, C[mi][ni][1] + b1f);
            float* p1 = out + (size_t)(gm + 8) * Edim + gc;
            *(float2*)p1 = make_float2(C[mi][ni][2] + b0f, C[mi][ni][3] + b1f);
        }
}

extern "C" void kernel_launch(void* const* d_in, const int* in_sizes, int n_in,
                              void* d_out, int out_size)
{
    const float* x  = (const float*)d_in[0];
    const float* Wq = (const float*)d_in[1];
    const float* bq = (const float*)d_in[2];
    const float* Wk = (const float*)d_in[3];
    const float* bk = (const float*)d_in[4];
    const float* Wv = (const float*)d_in[5];
    const float* bv = (const float*)d_in[6];
    const float* Wo = (const float*)d_in[7];
    const float* bo = (const float*)d_in[8];
    float* out = (float*)d_out;

    static bool attr_set = false;
    if (!attr_set) {
        cudaFuncSetAttribute(attn_kernel,
            cudaFuncAttributeMaxDynamicSharedMemorySize, ATTN_SMEM_BYTES);
        attr_set = true;
    }

    const int nW = Hn * Edim * DHd / 4;           // 262,144 float4s per weight
    dim3 g0((nW + 255) / 256, 4);
    split4_kernel<<<g0, 256>>>(Wq, Wk, Wv, Wo, nW);

    dim3 g1(Mrows / 128, (3 * Hn * DHd) / 128);   // (32, 24)
    qkv_kernel<<<g1, 256>>>(x, bq, bk, bv);

    dim3 g2(Sdim / 128, Bsz * Hn);                // (16, 32)
    attn_kernel<<<g2, 256, ATTN_SMEM_BYTES>>>();

    dim3 g3(Mrows / 128, Edim / 128);             // (32, 8)
    outproj_kernel<<<g3, 256>>>(bo, out);
}

// round 13
// speedup vs baseline: 2.0767x; 1.2099x over previous
#include <cuda_runtime.h>
#include <cuda_bf16.h>
#include <cuda_fp16.h>
#include <math.h>

#define Bsz 2
#define Sdim 2048
#define Edim 1024
#define Hn 16
#define DHd 64
#define Adim 1024
#define Mrows (Bsz * Sdim)  // 4096

typedef unsigned short ushort_t;

// Scratch (allocation-free rule: __device__ globals)
__device__ __align__(256) float    g_Q [(size_t)Bsz * Hn * Sdim * DHd];  // [B,H,S,DH]
__device__ __align__(256) ushort_t g_Kf[(size_t)Bsz * Hn * Sdim * DHd];  // K fp16
__device__ __align__(256) ushort_t g_Vf[(size_t)Bsz * Hn * Sdim * DHd];  // V fp16
__device__ __align__(256) float    g_O [(size_t)Bsz * Sdim * Adim];      // [B,S,A]
// pre-converted weights (single fp16)
__device__ __align__(256) ushort_t g_Wqf[(size_t)Hn * Edim * DHd];
__device__ __align__(256) ushort_t g_Wkf[(size_t)Hn * Edim * DHd];
__device__ __align__(256) ushort_t g_Wvf[(size_t)Hn * Edim * DHd];
__device__ __align__(256) ushort_t g_Wof[(size_t)Adim * Edim];

// ---- mma.sync helpers --------------------------------------------------
__device__ __forceinline__ void ldsm_x4(unsigned* r, const void* p) {
    unsigned addr = (unsigned)__cvta_generic_to_shared(p);
    asm volatile("ldmatrix.sync.aligned.m8n8.x4.shared.b16 {%0,%1,%2,%3}, [%4];"
        : "=r"(r[0]), "=r"(r[1]), "=r"(r[2]), "=r"(r[3]) : "r"(addr));
}
__device__ __forceinline__ void ldsm_x4_t(unsigned* r, const void* p) {
    unsigned addr = (unsigned)__cvta_generic_to_shared(p);
    asm volatile("ldmatrix.sync.aligned.m8n8.x4.trans.shared.b16 {%0,%1,%2,%3}, [%4];"
        : "=r"(r[0]), "=r"(r[1]), "=r"(r[2]), "=r"(r[3]) : "r"(addr));
}
__device__ __forceinline__ void mma_f16(float* c, const unsigned* a, const unsigned* b) {
    asm volatile("mma.sync.aligned.m16n8k16.row.col.f32.f16.f16.f32 "
        "{%0,%1,%2,%3}, {%4,%5,%6,%7}, {%8,%9}, {%0,%1,%2,%3};"
        : "+f"(c[0]), "+f"(c[1]), "+f"(c[2]), "+f"(c[3])
        : "r"(a[0]), "r"(a[1]), "r"(a[2]), "r"(a[3]), "r"(b[0]), "r"(b[1]));
}
// fp16 hi/lo pair
__device__ __forceinline__ void hilo_pair_f16(float x, float y, unsigned& h, unsigned& l) {
    __half hx = __float2half_rn(x), hy = __float2half_rn(y);
    float rx = x - __half2float(hx), ry = y - __half2float(hy);
    __half lx = __float2half_rn(rx), ly = __float2half_rn(ry);
    h = (unsigned)__half_as_ushort(hx) | ((unsigned)__half_as_ushort(hy) << 16);
    l = (unsigned)__half_as_ushort(lx) | ((unsigned)__half_as_ushort(ly) << 16);
}
__device__ __forceinline__ unsigned pkf16(float x, float y) {
    __half2 h = __floats2half2_rn(x, y);
    return *(unsigned*)&h;
}
__device__ __forceinline__ float ex2f(float x) {
    float y; asm("ex2.approx.ftz.f32 %0, %1;" : "=f"(y) : "f"(x)); return y;
}
// ---- cp.async ----
__device__ __forceinline__ void cp_async16(void* smem_dst, const void* gmem_src) {
    unsigned d = (unsigned)__cvta_generic_to_shared(smem_dst);
    asm volatile("cp.async.cg.shared.global [%0], [%1], 16;" :: "r"(d), "l"(gmem_src));
}
__device__ __forceinline__ void cp_commit() {
    asm volatile("cp.async.commit_group;" ::: "memory");
}
__device__ __forceinline__ void cp_wait0() {
    asm volatile("cp.async.wait_group 0;" ::: "memory");
}

// ---------------------------------------------------------------------------
// Kernel 0: convert all 4 weight matrices fp32 -> single fp16, ONE launch.
// ---------------------------------------------------------------------------
__global__ __launch_bounds__(256) void split4_kernel(
    const float* __restrict__ s0, const float* __restrict__ s1,
    const float* __restrict__ s2, const float* __restrict__ s3, int n4)
{
    int i = blockIdx.x * blockDim.x + threadIdx.x;
    if (i >= n4) return;
    const float* src;
    ushort_t* df;
    switch (blockIdx.y) {
        case 0: src = s0; df = g_Wqf; break;
        case 1: src = s1; df = g_Wkf; break;
        case 2: src = s2; df = g_Wvf; break;
        default: src = s3; df = g_Wof; break;
    }
    float4 v = *(const float4*)(src + (size_t)i * 4);
    *(uint2*)(df + (size_t)i * 4) = make_uint2(pkf16(v.x, v.y), pkf16(v.z, v.w));
}

// ---------------------------------------------------------------------------
// Kernel 1: fused QKV projection. A (x) fp16 hi/lo (in-kernel convert),
// B single fp16 pure-copy. 2 MMAs per step. Epilogue: Q fp32, K/V fp16.
// ---------------------------------------------------------------------------
__global__ __launch_bounds__(256) void qkv_kernel(
    const float* __restrict__ x,
    const float* __restrict__ bq, const float* __restrict__ bk,
    const float* __restrict__ bv)
{
    __shared__ ushort_t As_h[2][128][24];
    __shared__ ushort_t As_l[2][128][24];
    __shared__ ushort_t Bs_f[2][16][136];

    const int tid = threadIdx.x;
    const int lane = tid & 31;
    const int warp = tid >> 5;
    const int wm = warp & 1;
    const int wn = warp >> 1;
    const int m0 = blockIdx.x * 128;
    const int n0 = blockIdx.y * 128;
    const int z = n0 >> 10;
    const ushort_t* Wf = (z == 0 ? g_Wqf : (z == 1 ? g_Wkf : g_Wvf));
    const float* bias  = (z == 0 ? bq : (z == 1 ? bk : bv));

    const int arow = tid >> 1;
    const int apart = (tid & 1) * 8;
    const float* Ag = x + (size_t)(m0 + arow) * Edim + apart;
    const int bkr = tid >> 4;
    const int bj = (tid & 15) * 8;
    const int cB = n0 + bj;
    const ushort_t* Bgf = Wf + (size_t)((cB >> 6) & 15) * (Edim * DHd) + (cB & 63);

    float C[4][4][4];
#pragma unroll
    for (int i = 0; i < 4; i++)
#pragma unroll
        for (int j = 0; j < 4; j++)
#pragma unroll
            for (int e = 0; e < 4; e++) C[i][j][e] = 0.f;

    float4 a0r, a1r;
    uint4 bF;
    a0r = *(const float4*)(Ag);
    a1r = *(const float4*)(Ag + 4);
    bF = *(const uint4*)(Bgf + (size_t)bkr * DHd);
    {
        unsigned h0,l0,h1,l1,h2,l2,h3,l3;
        hilo_pair_f16(a0r.x, a0r.y, h0, l0);
        hilo_pair_f16(a0r.z, a0r.w, h1, l1);
        hilo_pair_f16(a1r.x, a1r.y, h2, l2);
        hilo_pair_f16(a1r.z, a1r.w, h3, l3);
        *(uint4*)&As_h[0][arow][apart] = make_uint4(h0, h1, h2, h3);
        *(uint4*)&As_l[0][arow][apart] = make_uint4(l0, l1, l2, l3);
        *(uint4*)&Bs_f[0][bkr][bj] = bF;
    }
    __syncthreads();

    const int lrow = lane & 15;
    const int lkoff = (lane >> 4) * 8;

    int buf = 0;
    for (int k0 = 0; k0 < Edim; k0 += 16) {
        const bool more = (k0 + 16) < Edim;
        if (more) {
            a0r = *(const float4*)(Ag + k0 + 16);
            a1r = *(const float4*)(Ag + k0 + 20);
            bF = *(const uint4*)(Bgf + (size_t)(k0 + 16 + bkr) * DHd);
        }

        unsigned a_hi[4][4], a_lo[4][4], b_f[4][2];
#pragma unroll
        for (int mi = 0; mi < 4; mi++) {
            ldsm_x4(a_hi[mi], &As_h[buf][wm * 64 + mi * 16 + lrow][lkoff]);
            ldsm_x4(a_lo[mi], &As_l[buf][wm * 64 + mi * 16 + lrow][lkoff]);
        }
#pragma unroll
        for (int np = 0; np < 2; np++) {
            unsigned r[4];
            ldsm_x4_t(r, &Bs_f[buf][lrow][wn * 32 + np * 16 + lkoff]);
            b_f[2*np][0] = r[0]; b_f[2*np][1] = r[1];
            b_f[2*np+1][0] = r[2]; b_f[2*np+1][1] = r[3];
        }
#pragma unroll
        for (int mi = 0; mi < 4; mi++)
#pragma unroll
            for (int ni = 0; ni < 4; ni++) {
                mma_f16(C[mi][ni], a_hi[mi], b_f[ni]);
                mma_f16(C[mi][ni], a_lo[mi], b_f[ni]);
            }

        if (more) {
            int nb = buf ^ 1;
            unsigned h0,l0,h1,l1,h2,l2,h3,l3;
            hilo_pair_f16(a0r.x, a0r.y, h0, l0);
            hilo_pair_f16(a0r.z, a0r.w, h1, l1);
            hilo_pair_f16(a1r.x, a1r.y, h2, l2);
            hilo_pair_f16(a1r.z, a1r.w, h3, l3);
            *(uint4*)&As_h[nb][arow][apart] = make_uint4(h0, h1, h2, h3);
            *(uint4*)&As_l[nb][arow][apart] = make_uint4(l0, l1, l2, l3);
            *(uint4*)&Bs_f[nb][bkr][bj] = bF;
        }
        __syncthreads();
        buf ^= 1;
    }

    // epilogue: Q fp32; K fp16; V fp16
#pragma unroll
    for (int mi = 0; mi < 4; mi++)
#pragma unroll
        for (int ni = 0; ni < 4; ni++) {
            int gm = m0 + wm * 64 + mi * 16 + (lane >> 2);
            int gc = n0 + wn * 32 + ni * 8 + (lane & 3) * 2;
            float b0f = bias[gc & 1023];
            float b1f = bias[(gc & 1023) + 1];
            int h = (gc >> 6) & 15;
            int d = gc & 63;
            int bb = gm >> 11, s = gm & (Sdim - 1);
            size_t off0 = ((size_t)(bb * Hn + h) * Sdim + s) * DHd + d;
            int gm2 = gm + 8;
            int bb2 = gm2 >> 11, s2 = gm2 & (Sdim - 1);
            size_t off1 = ((size_t)(bb2 * Hn + h) * Sdim + s2) * DHd + d;
            float v00 = C[mi][ni][0] + b0f, v01 = C[mi][ni][1] + b1f;
            float v10 = C[mi][ni][2] + b0f, v11 = C[mi][ni][3] + b1f;
            if (z == 0) {
                *(float2*)(g_Q + off0) = make_float2(v00, v01);
                *(float2*)(g_Q + off1) = make_float2(v10, v11);
            } else {
                ushort_t* dst = (z == 1 ? g_Kf : g_Vf);
                *(unsigned*)(dst + off0) = pkf16(v00, v01);
                *(unsigned*)(dst + off1) = pkf16(v10, v11);
            }
        }
}

// ---------------------------------------------------------------------------
// Kernel 2: flash attention, fp16 (R12-proven, unchanged).
// ---------------------------------------------------------------------------
#define ATILE 4608            // 64*72 ushorts per array
#define ABUF  (2 * ATILE)
#define ATTN_SMEM_BYTES (2 * ABUF * 2)   // 36,864 B

__global__ __launch_bounds__(256) void attn_kernel()
{
    extern __shared__ ushort_t asmem[];

    const int bh = blockIdx.y;
    const int tid = threadIdx.x;
    const int lane = tid & 31;
    const int warp = tid >> 5;

    const float* Qp = g_Q + (size_t)bh * Sdim * DHd;
    const ushort_t* Kp = g_Kf + (size_t)bh * Sdim * DHd;
    const ushort_t* Vp = g_Vf + (size_t)bh * Sdim * DHd;

    const float SCALE = 0.125f * 1.4426950408889634f;

    unsigned aq_h[4][4], aq_l[4][4];
    {
        const int r0 = blockIdx.x * 128 + warp * 16 + (lane >> 2);
        const int r1 = r0 + 8;
        const int cb = (lane & 3) * 2;
#pragma unroll
        for (int kk = 0; kk < 4; kk++) {
            float2 v00 = *(const float2*)(Qp + (size_t)r0 * DHd + kk * 16 + cb);
            float2 v01 = *(const float2*)(Qp + (size_t)r0 * DHd + kk * 16 + cb + 8);
            float2 v10 = *(const float2*)(Qp + (size_t)r1 * DHd + kk * 16 + cb);
            float2 v11 = *(const float2*)(Qp + (size_t)r1 * DHd + kk * 16 + cb + 8);
            hilo_pair_f16(v00.x * SCALE, v00.y * SCALE, aq_h[kk][0], aq_l[kk][0]);
            hilo_pair_f16(v10.x * SCALE, v10.y * SCALE, aq_h[kk][1], aq_l[kk][1]);
            hilo_pair_f16(v01.x * SCALE, v01.y * SCALE, aq_h[kk][2], aq_l[kk][2]);
            hilo_pair_f16(v11.x * SCALE, v11.y * SCALE, aq_h[kk][3], aq_l[kk][3]);
        }
    }

    float o[8][4];
#pragma unroll
    for (int i = 0; i < 8; i++)
#pragma unroll
        for (int e = 0; e < 4; e++) o[i][e] = 0.f;
    float m0_ = -INFINITY, m1_ = -INFINITY, l0_ = 0.f, l1_ = 0.f;

    const int l15 = lane & 15;
    const int lk8 = (lane >> 4) * 8;
    const int srow = tid >> 3;
    const int sc8 = (tid & 7) * 8;

#pragma unroll
    for (int i = 0; i < 2; i++) {
        int row = srow + i * 32;
        size_t goff = (size_t)row * DHd + sc8;
        int soff = row * 72 + sc8;
        cp_async16(&asmem[0 * ABUF + 0 * ATILE + soff], Kp + goff);
        cp_async16(&asmem[0 * ABUF + 1 * ATILE + soff], Vp + goff);
    }
    cp_commit();

    int buf = 0;
    for (int t0 = 0; t0 < Sdim; t0 += 64) {
        cp_wait0();
        __syncthreads();

        const ushort_t* Ks = asmem + buf * ABUF + 0 * ATILE;
        const ushort_t* Vs = asmem + buf * ABUF + 1 * ATILE;

        if (t0 + 64 < Sdim) {
            int nb = buf ^ 1;
#pragma unroll
            for (int i = 0; i < 2; i++) {
                int row = srow + i * 32;
                size_t goff = (size_t)(t0 + 64 + row) * DHd + sc8;
                int soff = row * 72 + sc8;
                cp_async16(&asmem[nb * ABUF + 0 * ATILE + soff], Kp + goff);
                cp_async16(&asmem[nb * ABUF + 1 * ATILE + soff], Vp + goff);
            }
            cp_commit();
        }

        float sc[8][4];
#pragma unroll
        for (int i = 0; i < 8; i++)
#pragma unroll
            for (int e = 0; e < 4; e++) sc[i][e] = 0.f;

#pragma unroll
        for (int kk = 0; kk < 4; kk++) {
#pragma unroll
            for (int pp = 0; pp < 4; pp++) {
                unsigned rk[4];
                ldsm_x4(rk, &Ks[(pp * 16 + l15) * 72 + kk * 16 + lk8]);
                unsigned bk0[2] = {rk[0], rk[2]}, bk1[2] = {rk[1], rk[3]};
                mma_f16(sc[2*pp],   aq_h[kk], bk0);
                mma_f16(sc[2*pp],   aq_l[kk], bk0);
                mma_f16(sc[2*pp+1], aq_h[kk], bk1);
                mma_f16(sc[2*pp+1], aq_l[kk], bk1);
            }
        }

        float mx0 = m0_, mx1 = m1_;
#pragma unroll
        for (int i = 0; i < 8; i++) {
            mx0 = fmaxf(mx0, fmaxf(sc[i][0], sc[i][1]));
            mx1 = fmaxf(mx1, fmaxf(sc[i][2], sc[i][3]));
        }
        mx0 = fmaxf(mx0, __shfl_xor_sync(0xffffffffu, mx0, 1));
        mx0 = fmaxf(mx0, __shfl_xor_sync(0xffffffffu, mx0, 2));
        mx1 = fmaxf(mx1, __shfl_xor_sync(0xffffffffu, mx1, 1));
        mx1 = fmaxf(mx1, __shfl_xor_sync(0xffffffffu, mx1, 2));
        if (mx0 > m0_) {
            float corr = ex2f(m0_ - mx0);
            m0_ = mx0; l0_ *= corr;
#pragma unroll
            for (int i = 0; i < 8; i++) { o[i][0] *= corr; o[i][1] *= corr; }
        }
        if (mx1 > m1_) {
            float corr = ex2f(m1_ - mx1);
            m1_ = mx1; l1_ *= corr;
#pragma unroll
            for (int i = 0; i < 8; i++) { o[i][2] *= corr; o[i][3] *= corr; }
        }
        float ts0 = 0.f, ts1 = 0.f;
#pragma unroll
        for (int i = 0; i < 8; i++) {
            sc[i][0] = ex2f(sc[i][0] - m0_);
            sc[i][1] = ex2f(sc[i][1] - m0_);
            sc[i][2] = ex2f(sc[i][2] - m1_);
            sc[i][3] = ex2f(sc[i][3] - m1_);
            ts0 += sc[i][0] + sc[i][1];
            ts1 += sc[i][2] + sc[i][3];
        }
        ts0 += __shfl_xor_sync(0xffffffffu, ts0, 1);
        ts0 += __shfl_xor_sync(0xffffffffu, ts0, 2);
        ts1 += __shfl_xor_sync(0xffffffffu, ts1, 1);
        ts1 += __shfl_xor_sync(0xffffffffu, ts1, 2);
        l0_ += ts0; l1_ += ts1;

        // --- O += P @ V: both single fp16 ---
#pragma unroll
        for (int ss = 0; ss < 4; ss++) {
            unsigned ap[4];
            ap[0] = pkf16(sc[2*ss][0],   sc[2*ss][1]);
            ap[1] = pkf16(sc[2*ss][2],   sc[2*ss][3]);
            ap[2] = pkf16(sc[2*ss+1][0], sc[2*ss+1][1]);
            ap[3] = pkf16(sc[2*ss+1][2], sc[2*ss+1][3]);
#pragma unroll
            for (int np = 0; np < 4; np++) {
                unsigned vv[4];
                ldsm_x4_t(vv, &Vs[(ss * 16 + l15) * 72 + np * 16 + lk8]);
                unsigned b0[2] = {vv[0], vv[1]}, b1[2] = {vv[2], vv[3]};
                mma_f16(o[2*np],   ap, b0);
                mma_f16(o[2*np+1], ap, b1);
            }
        }
        __syncthreads();
        buf ^= 1;
    }

    const float inv0 = 1.0f / l0_, inv1 = 1.0f / l1_;
    const int b = bh >> 4, h = bh & 15;
    const int r0 = blockIdx.x * 128 + warp * 16 + (lane >> 2);
    float* op0 = g_O + (size_t)(b * Sdim + r0) * Adim + h * DHd;
    float* op1 = g_O + (size_t)(b * Sdim + r0 + 8) * Adim + h * DHd;
#pragma unroll
    for (int np = 0; np < 8; np++) {
        int col = np * 8 + (lane & 3) * 2;
        *(float2*)(op0 + col) = make_float2(o[np][0] * inv0, o[np][1] * inv0);
        *(float2*)(op1 + col) = make_float2(o[np][2] * inv1, o[np][3] * inv1);
    }
}

// ---------------------------------------------------------------------------
// Kernel 3: output projection. A (g_O) fp16 hi/lo in-kernel, B (Wo) single
// fp16 pure-copy. 2 MMAs per step.
// ---------------------------------------------------------------------------
__global__ __launch_bounds__(256) void outproj_kernel(
    const float* __restrict__ bo, float* __restrict__ out)
{
    __shared__ ushort_t As_h[2][128][24];
    __shared__ ushort_t As_l[2][128][24];
    __shared__ ushort_t Bs_f[2][16][136];

    const int tid = threadIdx.x;
    const int lane = tid & 31;
    const int warp = tid >> 5;
    const int wm = warp & 1;
    const int wn = warp >> 1;
    const int m0 = blockIdx.x * 128;
    const int n0 = blockIdx.y * 128;

    const int arow = tid >> 1;
    const int apart = (tid & 1) * 8;
    const float* Ag = g_O + (size_t)(m0 + arow) * Adim + apart;
    const int bkr = tid >> 4;
    const int bj = (tid & 15) * 8;
    const ushort_t* Bgf = g_Wof + n0 + bj;

    float C[4][4][4];
#pragma unroll
    for (int i = 0; i < 4; i++)
#pragma unroll
        for (int j = 0; j < 4; j++)
#pragma unroll
            for (int e = 0; e < 4; e++) C[i][j][e] = 0.f;

    float4 a0r, a1r;
    uint4 bF;
    a0r = *(const float4*)(Ag);
    a1r = *(const float4*)(Ag + 4);
    bF = *(const uint4*)(Bgf + (size_t)bkr * Edim);
    {
        unsigned h0,l0,h1,l1,h2,l2,h3,l3;
        hilo_pair_f16(a0r.x, a0r.y, h0, l0);
        hilo_pair_f16(a0r.z, a0r.w, h1, l1);
        hilo_pair_f16(a1r.x, a1r.y, h2, l2);
        hilo_pair_f16(a1r.z, a1r.w, h3, l3);
        *(uint4*)&As_h[0][arow][apart] = make_uint4(h0, h1, h2, h3);
        *(uint4*)&As_l[0][arow][apart] = make_uint4(l0, l1, l2, l3);
        *(uint4*)&Bs_f[0][bkr][bj] = bF;
    }
    __syncthreads();

    const int lrow = lane & 15;
    const int lkoff = (lane >> 4) * 8;

    int buf = 0;
    for (int k0 = 0; k0 < Adim; k0 += 16) {
        const bool more = (k0 + 16) < Adim;
        if (more) {
            a0r = *(const float4*)(Ag + k0 + 16);
            a1r = *(const float4*)(Ag + k0 + 20);
            bF = *(const uint4*)(Bgf + (size_t)(k0 + 16 + bkr) * Edim);
        }

        unsigned a_hi[4][4], a_lo[4][4], b_f[4][2];
#pragma unroll
        for (int mi = 0; mi < 4; mi++) {
            ldsm_x4(a_hi[mi], &As_h[buf][wm * 64 + mi * 16 + lrow][lkoff]);
            ldsm_x4(a_lo[mi], &As_l[buf][wm * 64 + mi * 16 + lrow][lkoff]);
        }
#pragma unroll
        for (int np = 0; np < 2; np++) {
            unsigned r[4];
            ldsm_x4_t(r, &Bs_f[buf][lrow][wn * 32 + np * 16 + lkoff]);
            b_f[2*np][0] = r[0]; b_f[2*np][1] = r[1];
            b_f[2*np+1][0] = r[2]; b_f[2*np+1][1] = r[3];
        }
#pragma unroll
        for (int mi = 0; mi < 4; mi++)
#pragma unroll
            for (int ni = 0; ni < 4; ni++) {
                mma_f16(C[mi][ni], a_hi[mi], b_f[ni]);
                mma_f16(C[mi][ni], a_lo[mi], b_f[ni]);
            }

        if (more) {
            int nb = buf ^ 1;
            unsigned h0,l0,h1,l1,h2,l2,h3,l3;
            hilo_pair_f16(a0r.x, a0r.y, h0, l0);
            hilo_pair_f16(a0r.z, a0r.w, h1, l1);
            hilo_pair_f16(a1r.x, a1r.y, h2, l2);
            hilo_pair_f16(a1r.z, a1r.w, h3, l3);
            *(uint4*)&As_h[nb][arow][apart] = make_uint4(h0, h1, h2, h3);
            *(uint4*)&As_l[nb][arow][apart] = make_uint4(l0, l1, l2, l3);
            *(uint4*)&Bs_f[nb][bkr][bj] = bF;
        }
        __syncthreads();
        buf ^= 1;
    }

#pragma unroll
    for (int mi = 0; mi < 4; mi++)
#pragma unroll
        for (int ni = 0; ni < 4; ni++) {
            int gm = m0 + wm * 64 + mi * 16 + (lane >> 2);
            int gc = n0 + wn * 32 + ni * 8 + (lane & 3) * 2;
            float b0f = bo[gc], b1f = bo[gc + 1];
            float* p0 = out + (size_t)gm * Edim + gc;
            *(float2*)p0 = make_float2(C[mi][ni][0] + b0f, C[mi][ni][1] + b1f);
            float* p1 = out + (size_t)(gm + 8) * Edim + gc;
            *(float2*)p1 = make_float2(C[mi][ni][2] + b0f, C[mi][ni][3] + b1f);
        }
}

extern "C" void kernel_launch(void* const* d_in, const int* in_sizes, int n_in,
                              void* d_out, int out_size)
{
    const float* x  = (const float*)d_in[0];
    const float* Wq = (const float*)d_in[1];
    const float* bq = (const float*)d_in[2];
    const float* Wk = (const float*)d_in[3];
    const float* bk = (const float*)d_in[4];
    const float* Wv = (const float*)d_in[5];
    const float* bv = (const float*)d_in[6];
    const float* Wo = (const float*)d_in[7];
    const float* bo = (const float*)d_in[8];
    float* out = (float*)d_out;

    static bool attr_set = false;
    if (!attr_set) {
        cudaFuncSetAttribute(attn_kernel,
            cudaFuncAttributeMaxDynamicSharedMemorySize, ATTN_SMEM_BYTES);
        attr_set = true;
    }

    const int nW = Hn * Edim * DHd / 4;           // 262,144 float4s per weight
    dim3 g0((nW + 255) / 256, 4);
    split4_kernel<<<g0, 256>>>(Wq, Wk, Wv, Wo, nW);

    dim3 g1(Mrows / 128, (3 * Hn * DHd) / 128);   // (32, 24)
    qkv_kernel<<<g1, 256>>>(x, bq, bk, bv);

    dim3 g2(Sdim / 128, Bsz * Hn);                // (16, 32)
    attn_kernel<<<g2, 256, ATTN_SMEM_BYTES>>>();

    dim3 g3(Mrows / 128, Edim / 128);             // (32, 8)
    outproj_kernel<<<g3, 256>>>(bo, out);
}

// round 14
// speedup vs baseline: 2.5734x; 1.2391x over previous
#include <cuda_runtime.h>
#include <cuda_bf16.h>
#include <cuda_fp16.h>
#include <math.h>

#define Bsz 2
#define Sdim 2048
#define Edim 1024
#define Hn 16
#define DHd 64
#define Adim 1024
#define Mrows (Bsz * Sdim)  // 4096

typedef unsigned short ushort_t;

// Scratch (allocation-free rule: __device__ globals)
__device__ __align__(256) float    g_Q [(size_t)Bsz * Hn * Sdim * DHd];  // [B,H,S,DH] fp32
__device__ __align__(256) ushort_t g_Kf[(size_t)Bsz * Hn * Sdim * DHd];  // K fp16
__device__ __align__(256) ushort_t g_Vf[(size_t)Bsz * Hn * Sdim * DHd];  // V fp16
__device__ __align__(256) ushort_t g_Of[(size_t)Bsz * Sdim * Adim];      // attn out fp16
// pre-converted inputs (single fp16)
__device__ __align__(256) ushort_t g_xf [(size_t)Mrows * Edim];
__device__ __align__(256) ushort_t g_Wqf[(size_t)Hn * Edim * DHd];
__device__ __align__(256) ushort_t g_Wkf[(size_t)Hn * Edim * DHd];
__device__ __align__(256) ushort_t g_Wvf[(size_t)Hn * Edim * DHd];
__device__ __align__(256) ushort_t g_Wof[(size_t)Adim * Edim];

// ---- mma.sync helpers --------------------------------------------------
__device__ __forceinline__ void ldsm_x4(unsigned* r, const void* p) {
    unsigned addr = (unsigned)__cvta_generic_to_shared(p);
    asm volatile("ldmatrix.sync.aligned.m8n8.x4.shared.b16 {%0,%1,%2,%3}, [%4];"
        : "=r"(r[0]), "=r"(r[1]), "=r"(r[2]), "=r"(r[3]) : "r"(addr));
}
__device__ __forceinline__ void ldsm_x4_t(unsigned* r, const void* p) {
    unsigned addr = (unsigned)__cvta_generic_to_shared(p);
    asm volatile("ldmatrix.sync.aligned.m8n8.x4.trans.shared.b16 {%0,%1,%2,%3}, [%4];"
        : "=r"(r[0]), "=r"(r[1]), "=r"(r[2]), "=r"(r[3]) : "r"(addr));
}
__device__ __forceinline__ void mma_f16(float* c, const unsigned* a, const unsigned* b) {
    asm volatile("mma.sync.aligned.m16n8k16.row.col.f32.f16.f16.f32 "
        "{%0,%1,%2,%3}, {%4,%5,%6,%7}, {%8,%9}, {%0,%1,%2,%3};"
        : "+f"(c[0]), "+f"(c[1]), "+f"(c[2]), "+f"(c[3])
        : "r"(a[0]), "r"(a[1]), "r"(a[2]), "r"(a[3]), "r"(b[0]), "r"(b[1]));
}
// fp16 hi/lo pair (attention Q only)
__device__ __forceinline__ void hilo_pair_f16(float x, float y, unsigned& h, unsigned& l) {
    __half hx = __float2half_rn(x), hy = __float2half_rn(y);
    float rx = x - __half2float(hx), ry = y - __half2float(hy);
    __half lx = __float2half_rn(rx), ly = __float2half_rn(ry);
    h = (unsigned)__half_as_ushort(hx) | ((unsigned)__half_as_ushort(hy) << 16);
    l = (unsigned)__half_as_ushort(lx) | ((unsigned)__half_as_ushort(ly) << 16);
}
__device__ __forceinline__ unsigned pkf16(float x, float y) {
    __half2 h = __floats2half2_rn(x, y);
    return *(unsigned*)&h;
}
__device__ __forceinline__ float ex2f(float x) {
    float y; asm("ex2.approx.ftz.f32 %0, %1;" : "=f"(y) : "f"(x)); return y;
}
// ---- cp.async ----
__device__ __forceinline__ void cp_async16(void* smem_dst, const void* gmem_src) {
    unsigned d = (unsigned)__cvta_generic_to_shared(smem_dst);
    asm volatile("cp.async.cg.shared.global [%0], [%1], 16;" :: "r"(d), "l"(gmem_src));
}
__device__ __forceinline__ void cp_commit() {
    asm volatile("cp.async.commit_group;" ::: "memory");
}
__device__ __forceinline__ void cp_wait0() {
    asm volatile("cp.async.wait_group 0;" ::: "memory");
}

// ---------------------------------------------------------------------------
// Kernel 0: convert x + 4 weights fp32 -> single fp16, ONE launch.
// grid = (max_n4/256, 5). y=0..3: weights (n4=nW), y=4: x (n4=nX).
// ---------------------------------------------------------------------------
__global__ __launch_bounds__(256) void split5_kernel(
    const float* __restrict__ s0, const float* __restrict__ s1,
    const float* __restrict__ s2, const float* __restrict__ s3,
    const float* __restrict__ s4, int nW, int nX)
{
    int i = blockIdx.x * blockDim.x + threadIdx.x;
    const float* src;
    ushort_t* df;
    int n4;
    switch (blockIdx.y) {
        case 0: src = s0; df = g_Wqf; n4 = nW; break;
        case 1: src = s1; df = g_Wkf; n4 = nW; break;
        case 2: src = s2; df = g_Wvf; n4 = nW; break;
        case 3: src = s3; df = g_Wof; n4 = nW; break;
        default: src = s4; df = g_xf; n4 = nX; break;
    }
    if (i >= n4) return;
    float4 v = *(const float4*)(src + (size_t)i * 4);
    *(uint2*)(df + (size_t)i * 4) = make_uint2(pkf16(v.x, v.y), pkf16(v.z, v.w));
}

// ---------------------------------------------------------------------------
// Kernel 1: fused QKV projection, pure fp16 GEMM (1 MMA per step).
// A (x fp16) and B (W fp16) both pure-copy staged. Epilogue: Q fp32, K/V fp16.
// ---------------------------------------------------------------------------
__global__ __launch_bounds__(256) void qkv_kernel(
    const float* __restrict__ bq, const float* __restrict__ bk,
    const float* __restrict__ bv)
{
    __shared__ ushort_t As_f[2][128][24];
    __shared__ ushort_t Bs_f[2][16][136];

    const int tid = threadIdx.x;
    const int lane = tid & 31;
    const int warp = tid >> 5;
    const int wm = warp & 1;
    const int wn = warp >> 1;
    const int m0 = blockIdx.x * 128;
    const int n0 = blockIdx.y * 128;
    const int z = n0 >> 10;
    const ushort_t* Wf = (z == 0 ? g_Wqf : (z == 1 ? g_Wkf : g_Wvf));
    const float* bias  = (z == 0 ? bq : (z == 1 ? bk : bv));

    const int arow = tid >> 1;
    const int apart = (tid & 1) * 8;
    const ushort_t* Ag = g_xf + (size_t)(m0 + arow) * Edim + apart;
    const int bkr = tid >> 4;
    const int bj = (tid & 15) * 8;
    const int cB = n0 + bj;
    const ushort_t* Bgf = Wf + (size_t)((cB >> 6) & 15) * (Edim * DHd) + (cB & 63);

    float C[4][4][4];
#pragma unroll
    for (int i = 0; i < 4; i++)
#pragma unroll
        for (int j = 0; j < 4; j++)
#pragma unroll
            for (int e = 0; e < 4; e++) C[i][j][e] = 0.f;

    uint4 aF, bF;
    aF = *(const uint4*)(Ag);
    bF = *(const uint4*)(Bgf + (size_t)bkr * DHd);
    *(uint4*)&As_f[0][arow][apart] = aF;
    *(uint4*)&Bs_f[0][bkr][bj] = bF;
    __syncthreads();

    const int lrow = lane & 15;
    const int lkoff = (lane >> 4) * 8;

    int buf = 0;
    for (int k0 = 0; k0 < Edim; k0 += 16) {
        const bool more = (k0 + 16) < Edim;
        if (more) {
            aF = *(const uint4*)(Ag + k0 + 16);
            bF = *(const uint4*)(Bgf + (size_t)(k0 + 16 + bkr) * DHd);
        }

        unsigned a_f[4][4], b_f[4][2];
#pragma unroll
        for (int mi = 0; mi < 4; mi++)
            ldsm_x4(a_f[mi], &As_f[buf][wm * 64 + mi * 16 + lrow][lkoff]);
#pragma unroll
        for (int np = 0; np < 2; np++) {
            unsigned r[4];
            ldsm_x4_t(r, &Bs_f[buf][lrow][wn * 32 + np * 16 + lkoff]);
            b_f[2*np][0] = r[0]; b_f[2*np][1] = r[1];
            b_f[2*np+1][0] = r[2]; b_f[2*np+1][1] = r[3];
        }
#pragma unroll
        for (int mi = 0; mi < 4; mi++)
#pragma unroll
            for (int ni = 0; ni < 4; ni++)
                mma_f16(C[mi][ni], a_f[mi], b_f[ni]);

        if (more) {
            int nb = buf ^ 1;
            *(uint4*)&As_f[nb][arow][apart] = aF;
            *(uint4*)&Bs_f[nb][bkr][bj] = bF;
        }
        __syncthreads();
        buf ^= 1;
    }

    // epilogue: Q fp32; K fp16; V fp16
#pragma unroll
    for (int mi = 0; mi < 4; mi++)
#pragma unroll
        for (int ni = 0; ni < 4; ni++) {
            int gm = m0 + wm * 64 + mi * 16 + (lane >> 2);
            int gc = n0 + wn * 32 + ni * 8 + (lane & 3) * 2;
            float b0f = bias[gc & 1023];
            float b1f = bias[(gc & 1023) + 1];
            int h = (gc >> 6) & 15;
            int d = gc & 63;
            int bb = gm >> 11, s = gm & (Sdim - 1);
            size_t off0 = ((size_t)(bb * Hn + h) * Sdim + s) * DHd + d;
            int gm2 = gm + 8;
            int bb2 = gm2 >> 11, s2 = gm2 & (Sdim - 1);
            size_t off1 = ((size_t)(bb2 * Hn + h) * Sdim + s2) * DHd + d;
            float v00 = C[mi][ni][0] + b0f, v01 = C[mi][ni][1] + b1f;
            float v10 = C[mi][ni][2] + b0f, v11 = C[mi][ni][3] + b1f;
            if (z == 0) {
                *(float2*)(g_Q + off0) = make_float2(v00, v01);
                *(float2*)(g_Q + off1) = make_float2(v10, v11);
            } else {
                ushort_t* dst = (z == 1 ? g_Kf : g_Vf);
                *(unsigned*)(dst + off0) = pkf16(v00, v01);
                *(unsigned*)(dst + off1) = pkf16(v10, v11);
            }
        }
}

// ---------------------------------------------------------------------------
// Kernel 2: flash attention, fp16 (R12/R13-proven math). Epilogue now writes
// g_Of as fp16.
// ---------------------------------------------------------------------------
#define ATILE 4608            // 64*72 ushorts per array
#define ABUF  (2 * ATILE)
#define ATTN_SMEM_BYTES (2 * ABUF * 2)   // 36,864 B

__global__ __launch_bounds__(256) void attn_kernel()
{
    extern __shared__ ushort_t asmem[];

    const int bh = blockIdx.y;
    const int tid = threadIdx.x;
    const int lane = tid & 31;
    const int warp = tid >> 5;

    const float* Qp = g_Q + (size_t)bh * Sdim * DHd;
    const ushort_t* Kp = g_Kf + (size_t)bh * Sdim * DHd;
    const ushort_t* Vp = g_Vf + (size_t)bh * Sdim * DHd;

    const float SCALE = 0.125f * 1.4426950408889634f;

    unsigned aq_h[4][4], aq_l[4][4];
    {
        const int r0 = blockIdx.x * 128 + warp * 16 + (lane >> 2);
        const int r1 = r0 + 8;
        const int cb = (lane & 3) * 2;
#pragma unroll
        for (int kk = 0; kk < 4; kk++) {
            float2 v00 = *(const float2*)(Qp + (size_t)r0 * DHd + kk * 16 + cb);
            float2 v01 = *(const float2*)(Qp + (size_t)r0 * DHd + kk * 16 + cb + 8);
            float2 v10 = *(const float2*)(Qp + (size_t)r1 * DHd + kk * 16 + cb);
            float2 v11 = *(const float2*)(Qp + (size_t)r1 * DHd + kk * 16 + cb + 8);
            hilo_pair_f16(v00.x * SCALE, v00.y * SCALE, aq_h[kk][0], aq_l[kk][0]);
            hilo_pair_f16(v10.x * SCALE, v10.y * SCALE, aq_h[kk][1], aq_l[kk][1]);
            hilo_pair_f16(v01.x * SCALE, v01.y * SCALE, aq_h[kk][2], aq_l[kk][2]);
            hilo_pair_f16(v11.x * SCALE, v11.y * SCALE, aq_h[kk][3], aq_l[kk][3]);
        }
    }

    float o[8][4];
#pragma unroll
    for (int i = 0; i < 8; i++)
#pragma unroll
        for (int e = 0; e < 4; e++) o[i][e] = 0.f;
    float m0_ = -INFINITY, m1_ = -INFINITY, l0_ = 0.f, l1_ = 0.f;

    const int l15 = lane & 15;
    const int lk8 = (lane >> 4) * 8;
    const int srow = tid >> 3;
    const int sc8 = (tid & 7) * 8;

#pragma unroll
    for (int i = 0; i < 2; i++) {
        int row = srow + i * 32;
        size_t goff = (size_t)row * DHd + sc8;
        int soff = row * 72 + sc8;
        cp_async16(&asmem[0 * ABUF + 0 * ATILE + soff], Kp + goff);
        cp_async16(&asmem[0 * ABUF + 1 * ATILE + soff], Vp + goff);
    }
    cp_commit();

    int buf = 0;
    for (int t0 = 0; t0 < Sdim; t0 += 64) {
        cp_wait0();
        __syncthreads();

        const ushort_t* Ks = asmem + buf * ABUF + 0 * ATILE;
        const ushort_t* Vs = asmem + buf * ABUF + 1 * ATILE;

        if (t0 + 64 < Sdim) {
            int nb = buf ^ 1;
#pragma unroll
            for (int i = 0; i < 2; i++) {
                int row = srow + i * 32;
                size_t goff = (size_t)(t0 + 64 + row) * DHd + sc8;
                int soff = row * 72 + sc8;
                cp_async16(&asmem[nb * ABUF + 0 * ATILE + soff], Kp + goff);
                cp_async16(&asmem[nb * ABUF + 1 * ATILE + soff], Vp + goff);
            }
            cp_commit();
        }

        float sc[8][4];
#pragma unroll
        for (int i = 0; i < 8; i++)
#pragma unroll
            for (int e = 0; e < 4; e++) sc[i][e] = 0.f;

#pragma unroll
        for (int kk = 0; kk < 4; kk++) {
#pragma unroll
            for (int pp = 0; pp < 4; pp++) {
                unsigned rk[4];
                ldsm_x4(rk, &Ks[(pp * 16 + l15) * 72 + kk * 16 + lk8]);
                unsigned bk0[2] = {rk[0], rk[2]}, bk1[2] = {rk[1], rk[3]};
                mma_f16(sc[2*pp],   aq_h[kk], bk0);
                mma_f16(sc[2*pp],   aq_l[kk], bk0);
                mma_f16(sc[2*pp+1], aq_h[kk], bk1);
                mma_f16(sc[2*pp+1], aq_l[kk], bk1);
            }
        }

        float mx0 = m0_, mx1 = m1_;
#pragma unroll
        for (int i = 0; i < 8; i++) {
            mx0 = fmaxf(mx0, fmaxf(sc[i][0], sc[i][1]));
            mx1 = fmaxf(mx1, fmaxf(sc[i][2], sc[i][3]));
        }
        mx0 = fmaxf(mx0, __shfl_xor_sync(0xffffffffu, mx0, 1));
        mx0 = fmaxf(mx0, __shfl_xor_sync(0xffffffffu, mx0, 2));
        mx1 = fmaxf(mx1, __shfl_xor_sync(0xffffffffu, mx1, 1));
        mx1 = fmaxf(mx1, __shfl_xor_sync(0xffffffffu, mx1, 2));
        if (mx0 > m0_) {
            float corr = ex2f(m0_ - mx0);
            m0_ = mx0; l0_ *= corr;
#pragma unroll
            for (int i = 0; i < 8; i++) { o[i][0] *= corr; o[i][1] *= corr; }
        }
        if (mx1 > m1_) {
            float corr = ex2f(m1_ - mx1);
            m1_ = mx1; l1_ *= corr;
#pragma unroll
            for (int i = 0; i < 8; i++) { o[i][2] *= corr; o[i][3] *= corr; }
        }
        float ts0 = 0.f, ts1 = 0.f;
#pragma unroll
        for (int i = 0; i < 8; i++) {
            sc[i][0] = ex2f(sc[i][0] - m0_);
            sc[i][1] = ex2f(sc[i][1] - m0_);
            sc[i][2] = ex2f(sc[i][2] - m1_);
            sc[i][3] = ex2f(sc[i][3] - m1_);
            ts0 += sc[i][0] + sc[i][1];
            ts1 += sc[i][2] + sc[i][3];
        }
        ts0 += __shfl_xor_sync(0xffffffffu, ts0, 1);
        ts0 += __shfl_xor_sync(0xffffffffu, ts0, 2);
        ts1 += __shfl_xor_sync(0xffffffffu, ts1, 1);
        ts1 += __shfl_xor_sync(0xffffffffu, ts1, 2);
        l0_ += ts0; l1_ += ts1;

        // --- O += P @ V: both single fp16 ---
#pragma unroll
        for (int ss = 0; ss < 4; ss++) {
            unsigned ap[4];
            ap[0] = pkf16(sc[2*ss][0],   sc[2*ss][1]);
            ap[1] = pkf16(sc[2*ss][2],   sc[2*ss][3]);
            ap[2] = pkf16(sc[2*ss+1][0], sc[2*ss+1][1]);
            ap[3] = pkf16(sc[2*ss+1][2], sc[2*ss+1][3]);
#pragma unroll
            for (int np = 0; np < 4; np++) {
                unsigned vv[4];
                ldsm_x4_t(vv, &Vs[(ss * 16 + l15) * 72 + np * 16 + lk8]);
                unsigned b0[2] = {vv[0], vv[1]}, b1[2] = {vv[2], vv[3]};
                mma_f16(o[2*np],   ap, b0);
                mma_f16(o[2*np+1], ap, b1);
            }
        }
        __syncthreads();
        buf ^= 1;
    }

    // write normalized O as fp16 to g_Of
    const float inv0 = 1.0f / l0_, inv1 = 1.0f / l1_;
    const int b = bh >> 4, h = bh & 15;
    const int r0 = blockIdx.x * 128 + warp * 16 + (lane >> 2);
    size_t base0 = (size_t)(b * Sdim + r0) * Adim + h * DHd;
    size_t base1 = (size_t)(b * Sdim + r0 + 8) * Adim + h * DHd;
#pragma unroll
    for (int np = 0; np < 8; np++) {
        int col = np * 8 + (lane & 3) * 2;
        *(unsigned*)(g_Of + base0 + col) = pkf16(o[np][0] * inv0, o[np][1] * inv0);
        *(unsigned*)(g_Of + base1 + col) = pkf16(o[np][2] * inv1, o[np][3] * inv1);
    }
}

// ---------------------------------------------------------------------------
// Kernel 3: output projection, pure fp16 GEMM (1 MMA per step), both
// operands pure-copy staged.
// ---------------------------------------------------------------------------
__global__ __launch_bounds__(256) void outproj_kernel(
    const float* __restrict__ bo, float* __restrict__ out)
{
    __shared__ ushort_t As_f[2][128][24];
    __shared__ ushort_t Bs_f[2][16][136];

    const int tid = threadIdx.x;
    const int lane = tid & 31;
    const int warp = tid >> 5;
    const int wm = warp & 1;
    const int wn = warp >> 1;
    const int m0 = blockIdx.x * 128;
    const int n0 = blockIdx.y * 128;

    const int arow = tid >> 1;
    const int apart = (tid & 1) * 8;
    const ushort_t* Ag = g_Of + (size_t)(m0 + arow) * Adim + apart;
    const int bkr = tid >> 4;
    const int bj = (tid & 15) * 8;
    const ushort_t* Bgf = g_Wof + n0 + bj;

    float C[4][4][4];
#pragma unroll
    for (int i = 0; i < 4; i++)
#pragma unroll
        for (int j = 0; j < 4; j++)
#pragma unroll
            for (int e = 0; e < 4; e++) C[i][j][e] = 0.f;

    uint4 aF, bF;
    aF = *(const uint4*)(Ag);
    bF = *(const uint4*)(Bgf + (size_t)bkr * Edim);
    *(uint4*)&As_f[0][arow][apart] = aF;
    *(uint4*)&Bs_f[0][bkr][bj] = bF;
    __syncthreads();

    const int lrow = lane & 15;
    const int lkoff = (lane >> 4) * 8;

    int buf = 0;
    for (int k0 = 0; k0 < Adim; k0 += 16) {
        const bool more = (k0 + 16) < Adim;
        if (more) {
            aF = *(const uint4*)(Ag + k0 + 16);
            bF = *(const uint4*)(Bgf + (size_t)(k0 + 16 + bkr) * Edim);
        }

        unsigned a_f[4][4], b_f[4][2];
#pragma unroll
        for (int mi = 0; mi < 4; mi++)
            ldsm_x4(a_f[mi], &As_f[buf][wm * 64 + mi * 16 + lrow][lkoff]);
#pragma unroll
        for (int np = 0; np < 2; np++) {
            unsigned r[4];
            ldsm_x4_t(r, &Bs_f[buf][lrow][wn * 32 + np * 16 + lkoff]);
            b_f[2*np][0] = r[0]; b_f[2*np][1] = r[1];
            b_f[2*np+1][0] = r[2]; b_f[2*np+1][1] = r[3];
        }
#pragma unroll
        for (int mi = 0; mi < 4; mi++)
#pragma unroll
            for (int ni = 0; ni < 4; ni++)
                mma_f16(C[mi][ni], a_f[mi], b_f[ni]);

        if (more) {
            int nb = buf ^ 1;
            *(uint4*)&As_f[nb][arow][apart] = aF;
            *(uint4*)&Bs_f[nb][bkr][bj] = bF;
        }
        __syncthreads();
        buf ^= 1;
    }

#pragma unroll
    for (int mi = 0; mi < 4; mi++)
#pragma unroll
        for (int ni = 0; ni < 4; ni++) {
            int gm = m0 + wm * 64 + mi * 16 + (lane >> 2);
            int gc = n0 + wn * 32 + ni * 8 + (lane & 3) * 2;
            float b0f = bo[gc], b1f = bo[gc + 1];
            float* p0 = out + (size_t)gm * Edim + gc;
            *(float2*)p0 = make_float2(C[mi][ni][0] + b0f, C[mi][ni][1] + b1f);
            float* p1 = out + (size_t)(gm + 8) * Edim + gc;
            *(float2*)p1 = make_float2(C[mi][ni][2] + b0f, C[mi][ni][3] + b1f);
        }
}

extern "C" void kernel_launch(void* const* d_in, const int* in_sizes, int n_in,
                              void* d_out, int out_size)
{
    const float* x  = (const float*)d_in[0];
    const float* Wq = (const float*)d_in[1];
    const float* bq = (const float*)d_in[2];
    const float* Wk = (const float*)d_in[3];
    const float* bk = (const float*)d_in[4];
    const float* Wv = (const float*)d_in[5];
    const float* bv = (const float*)d_in[6];
    const float* Wo = (const float*)d_in[7];
    const float* bo = (const float*)d_in[8];
    float* out = (float*)d_out;

    static bool attr_set = false;
    if (!attr_set) {
        cudaFuncSetAttribute(attn_kernel,
            cudaFuncAttributeMaxDynamicSharedMemorySize, ATTN_SMEM_BYTES);
        attr_set = true;
    }

    const int nW = Hn * Edim * DHd / 4;           // 262,144 float4s per weight
    const int nX = Mrows * Edim / 4;              // 1,048,576 float4s
    dim3 g0((nX + 255) / 256, 5);
    split5_kernel<<<g0, 256>>>(Wq, Wk, Wv, Wo, x, nW, nX);

    dim3 g1(Mrows / 128, (3 * Hn * DHd) / 128);   // (32, 24)
    qkv_kernel<<<g1, 256>>>(bq, bk, bv);

    dim3 g2(Sdim / 128, Bsz * Hn);                // (16, 32)
    attn_kernel<<<g2, 256, ATTN_SMEM_BYTES>>>();

    dim3 g3(Mrows / 128, Edim / 128);             // (32, 8)
    outproj_kernel<<<g3, 256>>>(bo, out);
}